// round 11
// baseline (speedup 1.0000x reference)
#include <cuda_runtime.h>

#define NT 256
#define PA 196            // pitch for A, Q, V (mult of 4 -> LDS.128 rows)
#define PKT 68            // Kt pitch [d][m]
#define PS 66             // S pitch
#define PW 30             // W stage pitch

#define OFF_A   0         // 64 x PA : X/Y, then per-head O, then relu(M)
#define OFF_Q   12544     // 64 x PA : scaled Q (persists), then merge2 out T
#define OFF_KT  25088     // 192 x PKT : K transposed (per branch)
#define OFF_V   38144     // 64 x PA : full V (per branch)
#define OFF_S   50688     // 64 x PS (also W1 stage buffer during GEMMs)
#define OFF_W0  54912     // 96 x PW = 2880
#define OFF_W1  OFF_S
#define SMEM_FLOATS 57792 // 231168 bytes

typedef unsigned long long u64;
typedef union { float4 f; u64 u[2]; } v4u;

static __device__ __forceinline__ u64 pk2(float lo, float hi) {
    u64 r; asm("mov.b64 %0,{%1,%2};" : "=l"(r) : "f"(lo), "f"(hi)); return r;
}
static __device__ __forceinline__ void upk2(u64 v, float& lo, float& hi) {
    asm("mov.b64 {%0,%1}, %2;" : "=f"(lo), "=f"(hi) : "l"(v));
}
static __device__ __forceinline__ void fma2(u64& d, u64 a, u64 b) {
    asm("fma.rn.f32x2 %0, %1, %2, %0;" : "+l"(d) : "l"(a), "l"(b));
}

__device__ float g_bias[2 * 6 * 64 * 64];

__global__ void bias_pre_kernel(const float* __restrict__ rpb_x,
                                const float* __restrict__ rpb_y,
                                const int* __restrict__ rel_idx) {
    int i = blockIdx.x * blockDim.x + threadIdx.x;
    if (i >= 2 * 6 * 4096) return;
    int br = i / (6 * 4096);
    int h  = (i / 4096) % 6;
    int nm = i & 4095;
    const float* tab = br ? rpb_y : rpb_x;
    g_bias[i] = tab[rel_idx[nm] * 6 + h];
}

// 64x192 GEMM: dst[n][o] = (sum_c src[n][c]*W[o][c] + bias)*scl.
// Double-buffered 24-col W chunks, register prefetch, 1 sync per chunk.
// A loads are LDS.128 warp-broadcasts; W loads LDS.64.
// DST: 0 -> SMEM pitch PA, 1 -> global, 2 -> accumulate into M regs,
//      3 -> SMEM transposed (Kt[o][n], pitch PKT).
template<int DST>
static __device__ __forceinline__ void wide_gemm(
    float* sm, int srcOff, const float* __restrict__ Wg, int ldw,
    const float* __restrict__ bg, float scl,
    float* dstS, float* __restrict__ dstG, float (*M)[6], int t)
{
    const int tr = t >> 5, tc = t & 31, n0 = tr * 8;
    int wbase[9], soff[9];
    #pragma unroll
    for (int k = 0; k < 9; ++k) {
        int e = k * NT + t;
        int jj = e / 24, dd = e - jj * 24;
        wbase[k] = jj * ldw + dd;
        soff[k]  = jj * PW + dd;
    }
    #pragma unroll 1
    for (int half = 0; half < 2; ++half) {
        const float* Wh = Wg + (size_t)half * 96 * ldw;
        u64 acc[8][3];
        #pragma unroll
        for (int i = 0; i < 8; ++i) { acc[i][0] = 0; acc[i][1] = 0; acc[i][2] = 0; }

        float pre[9];
        #pragma unroll
        for (int k = 0; k < 9; ++k) pre[k] = Wh[wbase[k]];
        #pragma unroll
        for (int k = 0; k < 9; ++k) sm[OFF_W0 + soff[k]] = pre[k];
        __syncthreads();

        #pragma unroll 1
        for (int ch = 0; ch < 8; ++ch) {
            if (ch < 7) {
                #pragma unroll
                for (int k = 0; k < 9; ++k) pre[k] = Wh[wbase[k] + (ch + 1) * 24];
            }
            const float* sa = sm + srcOff + ch * 24;
            const float* wb = sm + ((ch & 1) ? OFF_W1 : OFF_W0);
            #pragma unroll
            for (int st = 0; st < 6; ++st) {      // 6 x 4-float steps = 24 cols
                v4u a4[8];
                u64 w2[3][2];
                #pragma unroll
                for (int i = 0; i < 8; ++i)
                    a4[i].f = *reinterpret_cast<const float4*>(
                        &sa[(n0 + i) * PA + 4 * st]);
                #pragma unroll
                for (int j = 0; j < 3; ++j) {
                    w2[j][0] = *reinterpret_cast<const u64*>(
                        &wb[(tc * 3 + j) * PW + 4 * st]);
                    w2[j][1] = *reinterpret_cast<const u64*>(
                        &wb[(tc * 3 + j) * PW + 4 * st + 2]);
                }
                #pragma unroll
                for (int i = 0; i < 8; ++i)
                    #pragma unroll
                    for (int j = 0; j < 3; ++j) {
                        fma2(acc[i][j], a4[i].u[0], w2[j][0]);
                        fma2(acc[i][j], a4[i].u[1], w2[j][1]);
                    }
            }
            if (ch < 7) {
                float* nb = sm + ((ch & 1) ? OFF_W0 : OFF_W1);
                #pragma unroll
                for (int k = 0; k < 9; ++k) nb[soff[k]] = pre[k];
            }
            __syncthreads();
        }

        #pragma unroll
        for (int j = 0; j < 3; ++j) {
            const int o = half * 96 + tc * 3 + j;
            #pragma unroll
            for (int i = 0; i < 8; ++i) {
                float lo, hi; upk2(acc[i][j], lo, hi);
                if (DST == 2) {
                    M[i][half * 3 + j] += lo + hi;
                } else {
                    float v = (lo + hi + bg[o]) * scl;
                    if (DST == 1)      dstG[(n0 + i) * 192 + o] = v;
                    else if (DST == 3) dstS[o * PKT + n0 + i]   = v;
                    else               dstS[(n0 + i) * PA + o]  = v;
                }
            }
        }
    }
}

__global__ void __launch_bounds__(NT, 1) fused_attn_kernel(
    const float* __restrict__ x, const float* __restrict__ y,
    const float* __restrict__ mask_x, const float* __restrict__ mask_y,
    const float* __restrict__ qkv_w, const float* __restrict__ qkv_b,
    const float* __restrict__ kv_w, const float* __restrict__ kv_b,
    const float* __restrict__ merge1_w, const float* __restrict__ merge1_b,
    const float* __restrict__ merge2_w, const float* __restrict__ merge2_b,
    const float* __restrict__ proj_w, const float* __restrict__ proj_b,
    float* __restrict__ out)
{
    extern __shared__ float sm[];
    const int t = threadIdx.x;
    const int w = blockIdx.x;
    const int tr = t >> 5, tc = t & 31;
    const int n0 = tr * 8;
    const float scale = 0.17677669529663687f;  // 32^-0.5

    // merge1 accumulator in registers; col = half*96 + tc*3 + j, rows n0..n0+7
    float M[8][6];
    #pragma unroll
    for (int half = 0; half < 2; ++half)
        #pragma unroll
        for (int j = 0; j < 3; ++j) {
            float b = merge1_b[half * 96 + tc * 3 + j];
            #pragma unroll
            for (int i = 0; i < 8; ++i) M[i][half * 3 + j] = b;
        }

    // attention-phase mappings (warp-local: warp wi owns rows 8wi..8wi+7)
    const int sr0 = (t >> 4) * 4;           // S: 4 rows
    const int sm0 = (t & 15) * 4;           // S: 4 m-cols
    const int pvrow = (t >> 5) * 8 + ((t & 31) >> 2);  // PV: 1 row
    const int pvd0  = (t & 3) * 8;                     // PV: 8 d-cols

    #pragma unroll 1
    for (int br = 0; br < 2; ++br) {
        // ---- load activation (X or Y) into A ----
        {
            const float* ap = (br ? y : x) + (size_t)w * 12288;
            for (int i = t; i < 12288; i += NT) {
                int n = i / 192, c = i - n * 192;
                sm[OFF_A + n * PA + c] = ap[i];
            }
        }
        // wide_gemm's first internal sync orders the A stores before reads.
        if (br == 0) {
            wide_gemm<0>(sm, OFF_A, qkv_w,             192, qkv_b,       scale, sm + OFF_Q,  nullptr, nullptr, t);
            wide_gemm<3>(sm, OFF_A, qkv_w + 192 * 192, 192, qkv_b + 192, 1.f,   sm + OFF_KT, nullptr, nullptr, t);
            wide_gemm<0>(sm, OFF_A, qkv_w + 384 * 192, 192, qkv_b + 384, 1.f,   sm + OFF_V,  nullptr, nullptr, t);
        } else {
            wide_gemm<3>(sm, OFF_A, kv_w,              192, kv_b,        1.f,   sm + OFF_KT, nullptr, nullptr, t);
            wide_gemm<0>(sm, OFF_A, kv_w + 192 * 192,  192, kv_b + 192,  1.f,   sm + OFF_V,  nullptr, nullptr, t);
        }
        __syncthreads();   // Q/Kt/V epilogue stores -> visible to attention

        const float* bias_base = g_bias + (size_t)(br * 6) * 4096;
        const float* maskp = (br ? mask_y : mask_x) + (size_t)(w & 1023) * 4096;

        // mask is head-invariant: hoist (S mapping)
        float4 mk4[4];
        #pragma unroll
        for (int i = 0; i < 4; ++i)
            mk4[i] = *reinterpret_cast<const float4*>(&maskp[(sr0 + i) * 64 + sm0]);

        #pragma unroll 1
        for (int h = 0; h < 6; ++h) {
            const int h32 = h * 32;

            // ---- S = Q Kt + bias + mask  (4 rows x 2 m-pairs, fma2 over m) ----
            {
                float4 bi4[4];
                const float* bb = bias_base + h * 4096;
                #pragma unroll
                for (int i = 0; i < 4; ++i)
                    bi4[i] = *reinterpret_cast<const float4*>(&bb[(sr0 + i) * 64 + sm0]);
                u64 acc[4][2];
                #pragma unroll
                for (int i = 0; i < 4; ++i) { acc[i][0] = 0; acc[i][1] = 0; }
                #pragma unroll 8
                for (int d = 0; d < 32; ++d) {
                    v4u kt;
                    kt.f = *reinterpret_cast<const float4*>(
                        &sm[OFF_KT + (h32 + d) * PKT + sm0]);
                    #pragma unroll
                    for (int i = 0; i < 4; ++i) {
                        float q = sm[OFF_Q + (sr0 + i) * PA + h32 + d];
                        u64 qq = pk2(q, q);
                        fma2(acc[i][0], qq, kt.u[0]);
                        fma2(acc[i][1], qq, kt.u[1]);
                    }
                }
                #pragma unroll
                for (int i = 0; i < 4; ++i) {
                    float s0, s1, s2, s3;
                    upk2(acc[i][0], s0, s1); upk2(acc[i][1], s2, s3);
                    s0 += bi4[i].x + mk4[i].x;  s1 += bi4[i].y + mk4[i].y;
                    s2 += bi4[i].z + mk4[i].z;  s3 += bi4[i].w + mk4[i].w;
                    *reinterpret_cast<u64*>(&sm[OFF_S + (sr0 + i) * PS + sm0])     = pk2(s0, s1);
                    *reinterpret_cast<u64*>(&sm[OFF_S + (sr0 + i) * PS + sm0 + 2]) = pk2(s2, s3);
                }
            }
            __syncwarp();

            // ---- softmax: warp wi owns rows 8wi..8wi+7 ----
            {
                const int wi = t >> 5, l = t & 31;
                #pragma unroll
                for (int rr = 0; rr < 8; rr++) {
                    int r = wi * 8 + rr;
                    float v0 = sm[OFF_S + r * PS + l];
                    float v1 = sm[OFF_S + r * PS + 32 + l];
                    float mx = fmaxf(v0, v1);
                    #pragma unroll
                    for (int o = 16; o > 0; o >>= 1)
                        mx = fmaxf(mx, __shfl_xor_sync(0xffffffffu, mx, o));
                    float e0 = __expf(v0 - mx), e1 = __expf(v1 - mx);
                    float s = e0 + e1;
                    #pragma unroll
                    for (int o = 16; o > 0; o >>= 1)
                        s += __shfl_xor_sync(0xffffffffu, s, o);
                    float inv = 1.0f / s;
                    sm[OFF_S + r * PS + l]      = e0 * inv;
                    sm[OFF_S + r * PS + 32 + l] = e1 * inv;
                }
            }
            __syncwarp();

            // ---- O = P V  (warp-local P rows) -> A region at col h32 ----
            {
                u64 acc[4];
                #pragma unroll
                for (int i = 0; i < 4; ++i) acc[i] = 0;
                #pragma unroll 4
                for (int m = 0; m < 64; ++m) {
                    float p = sm[OFF_S + pvrow * PS + m];
                    u64 pp = pk2(p, p);
                    v4u v0, v1;
                    v0.f = *reinterpret_cast<const float4*>(
                        &sm[OFF_V + m * PA + h32 + pvd0]);
                    v1.f = *reinterpret_cast<const float4*>(
                        &sm[OFF_V + m * PA + h32 + pvd0 + 4]);
                    fma2(acc[0], pp, v0.u[0]); fma2(acc[1], pp, v0.u[1]);
                    fma2(acc[2], pp, v1.u[0]); fma2(acc[3], pp, v1.u[1]);
                }
                #pragma unroll
                for (int i = 0; i < 4; ++i)
                    *reinterpret_cast<u64*>(
                        &sm[OFF_A + pvrow * PA + h32 + pvd0 + 2 * i]) = acc[i];
            }
            __syncwarp();   // own S rows reusable next head
        }  // heads

        __syncthreads();    // all warps' O complete before merge1 reads A

        // ---- merge1: M += O_all @ W1_branch^T (one wide GEMM, red=192) ----
        wide_gemm<2>(sm, OFF_A, merge1_w + br * 192, 384, nullptr, 1.f,
                     nullptr, nullptr, M, t);
        // ends with a full barrier (last chunk sync) -> safe to overwrite A
    }  // branches

    // ---- leaky relu(M) -> A (dead) ----
    #pragma unroll
    for (int half = 0; half < 2; ++half)
        #pragma unroll
        for (int j = 0; j < 3; ++j)
            #pragma unroll
            for (int i = 0; i < 8; ++i) {
                float v = M[i][half * 3 + j];
                v = v > 0.f ? v : 0.2f * v;
                sm[OFF_A + (n0 + i) * PA + half * 96 + tc * 3 + j] = v;
            }
    // merge2: T = relu(M) @ W2^T + b2 -> Q region
    wide_gemm<0>(sm, OFF_A, merge2_w, 192, merge2_b, 1.f, sm + OFF_Q, nullptr, nullptr, t);
    // proj: out = T @ Wp^T + pb -> global
    wide_gemm<1>(sm, OFF_Q, proj_w, 192, proj_b, 1.f, nullptr,
                 out + (size_t)w * 12288, nullptr, t);
}

extern "C" void kernel_launch(void* const* d_in, const int* in_sizes, int n_in,
                              void* d_out, int out_size) {
    const float* x        = (const float*)d_in[0];
    const float* y        = (const float*)d_in[1];
    const float* mask_x   = (const float*)d_in[2];
    const float* mask_y   = (const float*)d_in[3];
    const float* qkv_w    = (const float*)d_in[4];
    const float* qkv_b    = (const float*)d_in[5];
    const float* kv_w     = (const float*)d_in[6];
    const float* kv_b     = (const float*)d_in[7];
    const float* rpb_x    = (const float*)d_in[8];
    const float* rpb_y    = (const float*)d_in[9];
    const float* merge1_w = (const float*)d_in[10];
    const float* merge1_b = (const float*)d_in[11];
    const float* merge2_w = (const float*)d_in[12];
    const float* merge2_b = (const float*)d_in[13];
    const float* proj_w   = (const float*)d_in[14];
    const float* proj_b   = (const float*)d_in[15];
    const int*   rel_idx  = (const int*)d_in[16];
    float* out = (float*)d_out;

    cudaFuncSetAttribute(fused_attn_kernel,
                         cudaFuncAttributeMaxDynamicSharedMemorySize,
                         SMEM_FLOATS * 4);

    bias_pre_kernel<<<192, 256>>>(rpb_x, rpb_y, rel_idx);
    fused_attn_kernel<<<2048, NT, SMEM_FLOATS * 4>>>(
        x, y, mask_x, mask_y, qkv_w, qkv_b, kv_w, kv_b,
        merge1_w, merge1_b, merge2_w, merge2_b, proj_w, proj_b, out);
}

// round 12
// speedup vs baseline: 1.0008x; 1.0008x over previous
#include <cuda_runtime.h>

#define NT 256
#define PA 196            // pitch for A, Q, V (mult of 4 -> LDS.128 rows)
#define PKT 68            // Kt pitch [d][m]
#define PS 66             // S pitch
#define PW 30             // W stage pitch

#define OFF_A   0         // 64 x PA : X/Y, then per-head O, then relu(M)
#define OFF_Q   12544     // 64 x PA : scaled Q (persists), then merge2 out T
#define OFF_KT  25088     // 192 x PKT : K transposed (per branch)
#define OFF_V   38144     // 64 x PA : full V (per branch)
#define OFF_S   50688     // 64 x PS (also W1 stage buffer during GEMMs)
#define OFF_W0  54912     // 96 x PW = 2880
#define OFF_W1  OFF_S
#define SMEM_FLOATS 57792 // 231168 bytes

typedef unsigned long long u64;
typedef union { float4 f; u64 u[2]; } v4u;

static __device__ __forceinline__ u64 pk2(float lo, float hi) {
    u64 r; asm("mov.b64 %0,{%1,%2};" : "=l"(r) : "f"(lo), "f"(hi)); return r;
}
static __device__ __forceinline__ void upk2(u64 v, float& lo, float& hi) {
    asm("mov.b64 {%0,%1}, %2;" : "=f"(lo), "=f"(hi) : "l"(v));
}
static __device__ __forceinline__ void fma2(u64& d, u64 a, u64 b) {
    asm("fma.rn.f32x2 %0, %1, %2, %0;" : "+l"(d) : "l"(a), "l"(b));
}

__device__ float g_bias[2 * 6 * 64 * 64];

__global__ void bias_pre_kernel(const float* __restrict__ rpb_x,
                                const float* __restrict__ rpb_y,
                                const int* __restrict__ rel_idx) {
    int i = blockIdx.x * blockDim.x + threadIdx.x;
    if (i >= 2 * 6 * 4096) return;
    int br = i / (6 * 4096);
    int h  = (i / 4096) % 6;
    int nm = i & 4095;
    const float* tab = br ? rpb_y : rpb_x;
    g_bias[i] = tab[rel_idx[nm] * 6 + h];
}

// 64x192 GEMM: dst[n][o] = (sum_c src[n][c]*W[o][c] + bias)*scl.
// Double-buffered 24-col W chunks, register prefetch, 1 sync per chunk.
// A loads are LDS.128 warp-broadcasts; W loads LDS.64.
// DST: 0 -> SMEM pitch PA, 1 -> global, 2 -> accumulate into M regs,
//      3 -> SMEM transposed (Kt[o][n], pitch PKT).
template<int DST>
static __device__ __forceinline__ void wide_gemm(
    float* sm, int srcOff, const float* __restrict__ Wg, int ldw,
    const float* __restrict__ bg, float scl,
    float* dstS, float* __restrict__ dstG, float (*M)[6], int t)
{
    const int tr = t >> 5, tc = t & 31, n0 = tr * 8;
    int wbase[9], soff[9];
    #pragma unroll
    for (int k = 0; k < 9; ++k) {
        int e = k * NT + t;
        int jj = e / 24, dd = e - jj * 24;
        wbase[k] = jj * ldw + dd;
        soff[k]  = jj * PW + dd;
    }
    #pragma unroll 1
    for (int half = 0; half < 2; ++half) {
        const float* Wh = Wg + (size_t)half * 96 * ldw;
        u64 acc[8][3];
        #pragma unroll
        for (int i = 0; i < 8; ++i) { acc[i][0] = 0; acc[i][1] = 0; acc[i][2] = 0; }

        float pre[9];
        #pragma unroll
        for (int k = 0; k < 9; ++k) pre[k] = Wh[wbase[k]];
        #pragma unroll
        for (int k = 0; k < 9; ++k) sm[OFF_W0 + soff[k]] = pre[k];
        __syncthreads();

        #pragma unroll 1
        for (int ch = 0; ch < 8; ++ch) {
            if (ch < 7) {
                #pragma unroll
                for (int k = 0; k < 9; ++k) pre[k] = Wh[wbase[k] + (ch + 1) * 24];
            }
            const float* sa = sm + srcOff + ch * 24;
            const float* wb = sm + ((ch & 1) ? OFF_W1 : OFF_W0);
            #pragma unroll
            for (int st = 0; st < 6; ++st) {      // 6 x 4-float steps = 24 cols
                v4u a4[8];
                u64 w2[3][2];
                #pragma unroll
                for (int i = 0; i < 8; ++i)
                    a4[i].f = *reinterpret_cast<const float4*>(
                        &sa[(n0 + i) * PA + 4 * st]);
                #pragma unroll
                for (int j = 0; j < 3; ++j) {
                    w2[j][0] = *reinterpret_cast<const u64*>(
                        &wb[(tc * 3 + j) * PW + 4 * st]);
                    w2[j][1] = *reinterpret_cast<const u64*>(
                        &wb[(tc * 3 + j) * PW + 4 * st + 2]);
                }
                #pragma unroll
                for (int i = 0; i < 8; ++i)
                    #pragma unroll
                    for (int j = 0; j < 3; ++j) {
                        fma2(acc[i][j], a4[i].u[0], w2[j][0]);
                        fma2(acc[i][j], a4[i].u[1], w2[j][1]);
                    }
            }
            if (ch < 7) {
                float* nb = sm + ((ch & 1) ? OFF_W0 : OFF_W1);
                #pragma unroll
                for (int k = 0; k < 9; ++k) nb[soff[k]] = pre[k];
            }
            __syncthreads();
        }

        #pragma unroll
        for (int j = 0; j < 3; ++j) {
            const int o = half * 96 + tc * 3 + j;
            #pragma unroll
            for (int i = 0; i < 8; ++i) {
                float lo, hi; upk2(acc[i][j], lo, hi);
                if (DST == 2) {
                    M[i][half * 3 + j] += lo + hi;
                } else {
                    float v = (lo + hi + bg[o]) * scl;
                    if (DST == 1)      dstG[(n0 + i) * 192 + o] = v;
                    else if (DST == 3) dstS[o * PKT + n0 + i]   = v;
                    else               dstS[(n0 + i) * PA + o]  = v;
                }
            }
        }
    }
}

__global__ void __launch_bounds__(NT, 1) fused_attn_kernel(
    const float* __restrict__ x, const float* __restrict__ y,
    const float* __restrict__ mask_x, const float* __restrict__ mask_y,
    const float* __restrict__ qkv_w, const float* __restrict__ qkv_b,
    const float* __restrict__ kv_w, const float* __restrict__ kv_b,
    const float* __restrict__ merge1_w, const float* __restrict__ merge1_b,
    const float* __restrict__ merge2_w, const float* __restrict__ merge2_b,
    const float* __restrict__ proj_w, const float* __restrict__ proj_b,
    float* __restrict__ out)
{
    extern __shared__ float sm[];
    const int t = threadIdx.x;
    const int w = blockIdx.x;
    const int tr = t >> 5, tc = t & 31;
    const int n0 = tr * 8;
    const float scale = 0.17677669529663687f;  // 32^-0.5

    // merge1 accumulator in registers; col = half*96 + tc*3 + j, rows n0..n0+7
    float M[8][6];
    #pragma unroll
    for (int half = 0; half < 2; ++half)
        #pragma unroll
        for (int j = 0; j < 3; ++j) {
            float b = merge1_b[half * 96 + tc * 3 + j];
            #pragma unroll
            for (int i = 0; i < 8; ++i) M[i][half * 3 + j] = b;
        }

    // attention-phase mappings (warp-local: warp wi owns rows 8wi..8wi+7)
    const int sr0 = (t >> 4) * 4;           // S: 4 rows
    const int sm0 = (t & 15) * 4;           // S: 4 m-cols
    const int pvrow = (t >> 5) * 8 + ((t & 31) >> 2);  // PV: 1 row
    const int pvd0  = (t & 3) * 8;                     // PV: 8 d-cols

    #pragma unroll 1
    for (int br = 0; br < 2; ++br) {
        // ---- load activation (X or Y) into A ----
        {
            const float* ap = (br ? y : x) + (size_t)w * 12288;
            for (int i = t; i < 12288; i += NT) {
                int n = i / 192, c = i - n * 192;
                sm[OFF_A + n * PA + c] = ap[i];
            }
        }
        // wide_gemm's first internal sync orders the A stores before reads.
        if (br == 0) {
            wide_gemm<0>(sm, OFF_A, qkv_w,             192, qkv_b,       scale, sm + OFF_Q,  nullptr, nullptr, t);
            wide_gemm<3>(sm, OFF_A, qkv_w + 192 * 192, 192, qkv_b + 192, 1.f,   sm + OFF_KT, nullptr, nullptr, t);
            wide_gemm<0>(sm, OFF_A, qkv_w + 384 * 192, 192, qkv_b + 384, 1.f,   sm + OFF_V,  nullptr, nullptr, t);
        } else {
            wide_gemm<3>(sm, OFF_A, kv_w,              192, kv_b,        1.f,   sm + OFF_KT, nullptr, nullptr, t);
            wide_gemm<0>(sm, OFF_A, kv_w + 192 * 192,  192, kv_b + 192,  1.f,   sm + OFF_V,  nullptr, nullptr, t);
        }
        __syncthreads();   // Q/Kt/V epilogue stores -> visible to attention

        const float* bias_base = g_bias + (size_t)(br * 6) * 4096;
        const float* maskp = (br ? mask_y : mask_x) + (size_t)(w & 1023) * 4096;

        // mask is head-invariant: hoist (S mapping)
        float4 mk4[4];
        #pragma unroll
        for (int i = 0; i < 4; ++i)
            mk4[i] = *reinterpret_cast<const float4*>(&maskp[(sr0 + i) * 64 + sm0]);

        #pragma unroll 1
        for (int h = 0; h < 6; ++h) {
            const int h32 = h * 32;

            // ---- S = Q Kt + bias + mask  (4 rows x 2 m-pairs, fma2 over m) ----
            {
                float4 bi4[4];
                const float* bb = bias_base + h * 4096;
                #pragma unroll
                for (int i = 0; i < 4; ++i)
                    bi4[i] = *reinterpret_cast<const float4*>(&bb[(sr0 + i) * 64 + sm0]);
                u64 acc[4][2];
                #pragma unroll
                for (int i = 0; i < 4; ++i) { acc[i][0] = 0; acc[i][1] = 0; }
                #pragma unroll 8
                for (int d = 0; d < 32; ++d) {
                    v4u kt;
                    kt.f = *reinterpret_cast<const float4*>(
                        &sm[OFF_KT + (h32 + d) * PKT + sm0]);
                    #pragma unroll
                    for (int i = 0; i < 4; ++i) {
                        float q = sm[OFF_Q + (sr0 + i) * PA + h32 + d];
                        u64 qq = pk2(q, q);
                        fma2(acc[i][0], qq, kt.u[0]);
                        fma2(acc[i][1], qq, kt.u[1]);
                    }
                }
                #pragma unroll
                for (int i = 0; i < 4; ++i) {
                    float s0, s1, s2, s3;
                    upk2(acc[i][0], s0, s1); upk2(acc[i][1], s2, s3);
                    s0 += bi4[i].x + mk4[i].x;  s1 += bi4[i].y + mk4[i].y;
                    s2 += bi4[i].z + mk4[i].z;  s3 += bi4[i].w + mk4[i].w;
                    *reinterpret_cast<u64*>(&sm[OFF_S + (sr0 + i) * PS + sm0])     = pk2(s0, s1);
                    *reinterpret_cast<u64*>(&sm[OFF_S + (sr0 + i) * PS + sm0 + 2]) = pk2(s2, s3);
                }
            }
            __syncwarp();

            // ---- softmax: warp wi owns rows 8wi..8wi+7 ----
            {
                const int wi = t >> 5, l = t & 31;
                #pragma unroll
                for (int rr = 0; rr < 8; rr++) {
                    int r = wi * 8 + rr;
                    float v0 = sm[OFF_S + r * PS + l];
                    float v1 = sm[OFF_S + r * PS + 32 + l];
                    float mx = fmaxf(v0, v1);
                    #pragma unroll
                    for (int o = 16; o > 0; o >>= 1)
                        mx = fmaxf(mx, __shfl_xor_sync(0xffffffffu, mx, o));
                    float e0 = __expf(v0 - mx), e1 = __expf(v1 - mx);
                    float s = e0 + e1;
                    #pragma unroll
                    for (int o = 16; o > 0; o >>= 1)
                        s += __shfl_xor_sync(0xffffffffu, s, o);
                    float inv = 1.0f / s;
                    sm[OFF_S + r * PS + l]      = e0 * inv;
                    sm[OFF_S + r * PS + 32 + l] = e1 * inv;
                }
            }
            __syncwarp();

            // ---- O = P V  (warp-local P rows) -> A region at col h32 ----
            {
                u64 acc[4];
                #pragma unroll
                for (int i = 0; i < 4; ++i) acc[i] = 0;
                #pragma unroll 4
                for (int m = 0; m < 64; ++m) {
                    float p = sm[OFF_S + pvrow * PS + m];
                    u64 pp = pk2(p, p);
                    v4u v0, v1;
                    v0.f = *reinterpret_cast<const float4*>(
                        &sm[OFF_V + m * PA + h32 + pvd0]);
                    v1.f = *reinterpret_cast<const float4*>(
                        &sm[OFF_V + m * PA + h32 + pvd0 + 4]);
                    fma2(acc[0], pp, v0.u[0]); fma2(acc[1], pp, v0.u[1]);
                    fma2(acc[2], pp, v1.u[0]); fma2(acc[3], pp, v1.u[1]);
                }
                #pragma unroll
                for (int i = 0; i < 4; ++i)
                    *reinterpret_cast<u64*>(
                        &sm[OFF_A + pvrow * PA + h32 + pvd0 + 2 * i]) = acc[i];
            }
            __syncwarp();   // own S rows reusable next head
        }  // heads

        __syncthreads();    // all warps' O complete before merge1 reads A

        // ---- merge1: M += O_all @ W1_branch^T (one wide GEMM, red=192) ----
        wide_gemm<2>(sm, OFF_A, merge1_w + br * 192, 384, nullptr, 1.f,
                     nullptr, nullptr, M, t);
        // ends with a full barrier (last chunk sync) -> safe to overwrite A
    }  // branches

    // ---- leaky relu(M) -> A (dead) ----
    #pragma unroll
    for (int half = 0; half < 2; ++half)
        #pragma unroll
        for (int j = 0; j < 3; ++j)
            #pragma unroll
            for (int i = 0; i < 8; ++i) {
                float v = M[i][half * 3 + j];
                v = v > 0.f ? v : 0.2f * v;
                sm[OFF_A + (n0 + i) * PA + half * 96 + tc * 3 + j] = v;
            }
    // merge2: T = relu(M) @ W2^T + b2 -> Q region
    wide_gemm<0>(sm, OFF_A, merge2_w, 192, merge2_b, 1.f, sm + OFF_Q, nullptr, nullptr, t);
    // proj: out = T @ Wp^T + pb -> global
    wide_gemm<1>(sm, OFF_Q, proj_w, 192, proj_b, 1.f, nullptr,
                 out + (size_t)w * 12288, nullptr, t);
}

extern "C" void kernel_launch(void* const* d_in, const int* in_sizes, int n_in,
                              void* d_out, int out_size) {
    const float* x        = (const float*)d_in[0];
    const float* y        = (const float*)d_in[1];
    const float* mask_x   = (const float*)d_in[2];
    const float* mask_y   = (const float*)d_in[3];
    const float* qkv_w    = (const float*)d_in[4];
    const float* qkv_b    = (const float*)d_in[5];
    const float* kv_w     = (const float*)d_in[6];
    const float* kv_b     = (const float*)d_in[7];
    const float* rpb_x    = (const float*)d_in[8];
    const float* rpb_y    = (const float*)d_in[9];
    const float* merge1_w = (const float*)d_in[10];
    const float* merge1_b = (const float*)d_in[11];
    const float* merge2_w = (const float*)d_in[12];
    const float* merge2_b = (const float*)d_in[13];
    const float* proj_w   = (const float*)d_in[14];
    const float* proj_b   = (const float*)d_in[15];
    const int*   rel_idx  = (const int*)d_in[16];
    float* out = (float*)d_out;

    cudaFuncSetAttribute(fused_attn_kernel,
                         cudaFuncAttributeMaxDynamicSharedMemorySize,
                         SMEM_FLOATS * 4);

    bias_pre_kernel<<<192, 256>>>(rpb_x, rpb_y, rel_idx);
    fused_attn_kernel<<<2048, NT, SMEM_FLOATS * 4>>>(
        x, y, mask_x, mask_y, qkv_w, qkv_b, kv_w, kv_b,
        merge1_w, merge1_b, merge2_w, merge2_b, proj_w, proj_b, out);
}

// round 13
// speedup vs baseline: 1.0008x; 1.0000x over previous
#include <cuda_runtime.h>

#define NT 256
#define PA 196            // pitch for A, Q, V (mult of 4 -> LDS.128 rows)
#define PKT 68            // Kt pitch [d][m]
#define PS 66             // S pitch
#define PW 30             // W stage pitch

#define OFF_A   0         // 64 x PA : X/Y, then per-head O, then relu(M)
#define OFF_Q   12544     // 64 x PA : scaled Q (persists), then merge2 out T
#define OFF_KT  25088     // 192 x PKT : K transposed (per branch)
#define OFF_V   38144     // 64 x PA : full V (per branch)
#define OFF_S   50688     // 64 x PS (also W1 stage buffer during GEMMs)
#define OFF_W0  54912     // 96 x PW = 2880
#define OFF_W1  OFF_S
#define SMEM_FLOATS 57792 // 231168 bytes

typedef unsigned long long u64;
typedef union { float4 f; u64 u[2]; } v4u;

static __device__ __forceinline__ u64 pk2(float lo, float hi) {
    u64 r; asm("mov.b64 %0,{%1,%2};" : "=l"(r) : "f"(lo), "f"(hi)); return r;
}
static __device__ __forceinline__ void upk2(u64 v, float& lo, float& hi) {
    asm("mov.b64 {%0,%1}, %2;" : "=f"(lo), "=f"(hi) : "l"(v));
}
static __device__ __forceinline__ void fma2(u64& d, u64 a, u64 b) {
    asm("fma.rn.f32x2 %0, %1, %2, %0;" : "+l"(d) : "l"(a), "l"(b));
}

__device__ float g_bias[2 * 6 * 64 * 64];

__global__ void bias_pre_kernel(const float* __restrict__ rpb_x,
                                const float* __restrict__ rpb_y,
                                const int* __restrict__ rel_idx) {
    int i = blockIdx.x * blockDim.x + threadIdx.x;
    if (i >= 2 * 6 * 4096) return;
    int br = i / (6 * 4096);
    int h  = (i / 4096) % 6;
    int nm = i & 4095;
    const float* tab = br ? rpb_y : rpb_x;
    g_bias[i] = tab[rel_idx[nm] * 6 + h];
}

// 64x192 GEMM: dst[n][o] = (sum_c src[n][c]*W[o][c] + bias)*scl.
// Double-buffered 24-col W chunks, register prefetch, 1 sync per chunk.
// A loads are LDS.128 warp-broadcasts; W loads LDS.64.
// DST: 0 -> SMEM pitch PA, 1 -> global, 2 -> accumulate into M regs,
//      3 -> SMEM transposed (Kt[o][n], pitch PKT).
template<int DST>
static __device__ __forceinline__ void wide_gemm(
    float* sm, int srcOff, const float* __restrict__ Wg, int ldw,
    const float* __restrict__ bg, float scl,
    float* dstS, float* __restrict__ dstG, float (*M)[6], int t)
{
    const int tr = t >> 5, tc = t & 31, n0 = tr * 8;
    int wbase[9], soff[9];
    #pragma unroll
    for (int k = 0; k < 9; ++k) {
        int e = k * NT + t;
        int jj = e / 24, dd = e - jj * 24;
        wbase[k] = jj * ldw + dd;
        soff[k]  = jj * PW + dd;
    }
    #pragma unroll 1
    for (int half = 0; half < 2; ++half) {
        const float* Wh = Wg + (size_t)half * 96 * ldw;
        u64 acc[8][3];
        #pragma unroll
        for (int i = 0; i < 8; ++i) { acc[i][0] = 0; acc[i][1] = 0; acc[i][2] = 0; }

        float pre[9];
        #pragma unroll
        for (int k = 0; k < 9; ++k) pre[k] = Wh[wbase[k]];
        #pragma unroll
        for (int k = 0; k < 9; ++k) sm[OFF_W0 + soff[k]] = pre[k];
        __syncthreads();

        #pragma unroll 1
        for (int ch = 0; ch < 8; ++ch) {
            if (ch < 7) {
                #pragma unroll
                for (int k = 0; k < 9; ++k) pre[k] = Wh[wbase[k] + (ch + 1) * 24];
            }
            const float* sa = sm + srcOff + ch * 24;
            const float* wb = sm + ((ch & 1) ? OFF_W1 : OFF_W0);
            #pragma unroll
            for (int st = 0; st < 6; ++st) {      // 6 x 4-float steps = 24 cols
                v4u a4[8];
                u64 w2[3][2];
                #pragma unroll
                for (int i = 0; i < 8; ++i)
                    a4[i].f = *reinterpret_cast<const float4*>(
                        &sa[(n0 + i) * PA + 4 * st]);
                #pragma unroll
                for (int j = 0; j < 3; ++j) {
                    w2[j][0] = *reinterpret_cast<const u64*>(
                        &wb[(tc * 3 + j) * PW + 4 * st]);
                    w2[j][1] = *reinterpret_cast<const u64*>(
                        &wb[(tc * 3 + j) * PW + 4 * st + 2]);
                }
                #pragma unroll
                for (int i = 0; i < 8; ++i)
                    #pragma unroll
                    for (int j = 0; j < 3; ++j) {
                        fma2(acc[i][j], a4[i].u[0], w2[j][0]);
                        fma2(acc[i][j], a4[i].u[1], w2[j][1]);
                    }
            }
            if (ch < 7) {
                float* nb = sm + ((ch & 1) ? OFF_W0 : OFF_W1);
                #pragma unroll
                for (int k = 0; k < 9; ++k) nb[soff[k]] = pre[k];
            }
            __syncthreads();
        }

        #pragma unroll
        for (int j = 0; j < 3; ++j) {
            const int o = half * 96 + tc * 3 + j;
            #pragma unroll
            for (int i = 0; i < 8; ++i) {
                float lo, hi; upk2(acc[i][j], lo, hi);
                if (DST == 2) {
                    M[i][half * 3 + j] += lo + hi;
                } else {
                    float v = (lo + hi + bg[o]) * scl;
                    if (DST == 1)      dstG[(n0 + i) * 192 + o] = v;
                    else if (DST == 3) dstS[o * PKT + n0 + i]   = v;
                    else               dstS[(n0 + i) * PA + o]  = v;
                }
            }
        }
    }
}

__global__ void __launch_bounds__(NT, 1) fused_attn_kernel(
    const float* __restrict__ x, const float* __restrict__ y,
    const float* __restrict__ mask_x, const float* __restrict__ mask_y,
    const float* __restrict__ qkv_w, const float* __restrict__ qkv_b,
    const float* __restrict__ kv_w, const float* __restrict__ kv_b,
    const float* __restrict__ merge1_w, const float* __restrict__ merge1_b,
    const float* __restrict__ merge2_w, const float* __restrict__ merge2_b,
    const float* __restrict__ proj_w, const float* __restrict__ proj_b,
    float* __restrict__ out)
{
    extern __shared__ float sm[];
    const int t = threadIdx.x;
    const int w = blockIdx.x;
    const int tr = t >> 5, tc = t & 31;
    const int n0 = tr * 8;
    const float scale = 0.17677669529663687f;  // 32^-0.5

    // merge1 accumulator in registers; col = half*96 + tc*3 + j, rows n0..n0+7
    float M[8][6];
    #pragma unroll
    for (int half = 0; half < 2; ++half)
        #pragma unroll
        for (int j = 0; j < 3; ++j) {
            float b = merge1_b[half * 96 + tc * 3 + j];
            #pragma unroll
            for (int i = 0; i < 8; ++i) M[i][half * 3 + j] = b;
        }

    // attention-phase mappings (warp-local: warp wi owns rows 8wi..8wi+7)
    const int sr0 = (t >> 4) * 4;           // S: 4 rows
    const int sm0 = (t & 15) * 4;           // S: 4 m-cols
    const int pvrow = (t >> 5) * 8 + ((t & 31) >> 2);  // PV: 1 row
    const int pvd0  = (t & 3) * 8;                     // PV: 8 d-cols

    #pragma unroll 1
    for (int br = 0; br < 2; ++br) {
        // ---- load activation (X or Y) into A ----
        {
            const float* ap = (br ? y : x) + (size_t)w * 12288;
            for (int i = t; i < 12288; i += NT) {
                int n = i / 192, c = i - n * 192;
                sm[OFF_A + n * PA + c] = ap[i];
            }
        }
        // wide_gemm's first internal sync orders the A stores before reads.
        if (br == 0) {
            wide_gemm<0>(sm, OFF_A, qkv_w,             192, qkv_b,       scale, sm + OFF_Q,  nullptr, nullptr, t);
            wide_gemm<3>(sm, OFF_A, qkv_w + 192 * 192, 192, qkv_b + 192, 1.f,   sm + OFF_KT, nullptr, nullptr, t);
            wide_gemm<0>(sm, OFF_A, qkv_w + 384 * 192, 192, qkv_b + 384, 1.f,   sm + OFF_V,  nullptr, nullptr, t);
        } else {
            wide_gemm<3>(sm, OFF_A, kv_w,              192, kv_b,        1.f,   sm + OFF_KT, nullptr, nullptr, t);
            wide_gemm<0>(sm, OFF_A, kv_w + 192 * 192,  192, kv_b + 192,  1.f,   sm + OFF_V,  nullptr, nullptr, t);
        }
        __syncthreads();   // Q/Kt/V epilogue stores -> visible to attention

        const float* bias_base = g_bias + (size_t)(br * 6) * 4096;
        const float* maskp = (br ? mask_y : mask_x) + (size_t)(w & 1023) * 4096;

        // mask is head-invariant: hoist (S mapping)
        float4 mk4[4];
        #pragma unroll
        for (int i = 0; i < 4; ++i)
            mk4[i] = *reinterpret_cast<const float4*>(&maskp[(sr0 + i) * 64 + sm0]);

        #pragma unroll 1
        for (int h = 0; h < 6; ++h) {
            const int h32 = h * 32;

            // ---- S = Q Kt + bias + mask  (4 rows x 2 m-pairs, fma2 over m) ----
            {
                float4 bi4[4];
                const float* bb = bias_base + h * 4096;
                #pragma unroll
                for (int i = 0; i < 4; ++i)
                    bi4[i] = *reinterpret_cast<const float4*>(&bb[(sr0 + i) * 64 + sm0]);
                u64 acc[4][2];
                #pragma unroll
                for (int i = 0; i < 4; ++i) { acc[i][0] = 0; acc[i][1] = 0; }
                #pragma unroll 8
                for (int d = 0; d < 32; ++d) {
                    v4u kt;
                    kt.f = *reinterpret_cast<const float4*>(
                        &sm[OFF_KT + (h32 + d) * PKT + sm0]);
                    #pragma unroll
                    for (int i = 0; i < 4; ++i) {
                        float q = sm[OFF_Q + (sr0 + i) * PA + h32 + d];
                        u64 qq = pk2(q, q);
                        fma2(acc[i][0], qq, kt.u[0]);
                        fma2(acc[i][1], qq, kt.u[1]);
                    }
                }
                #pragma unroll
                for (int i = 0; i < 4; ++i) {
                    float s0, s1, s2, s3;
                    upk2(acc[i][0], s0, s1); upk2(acc[i][1], s2, s3);
                    s0 += bi4[i].x + mk4[i].x;  s1 += bi4[i].y + mk4[i].y;
                    s2 += bi4[i].z + mk4[i].z;  s3 += bi4[i].w + mk4[i].w;
                    *reinterpret_cast<u64*>(&sm[OFF_S + (sr0 + i) * PS + sm0])     = pk2(s0, s1);
                    *reinterpret_cast<u64*>(&sm[OFF_S + (sr0 + i) * PS + sm0 + 2]) = pk2(s2, s3);
                }
            }
            __syncwarp();

            // ---- softmax: warp wi owns rows 8wi..8wi+7 ----
            {
                const int wi = t >> 5, l = t & 31;
                #pragma unroll
                for (int rr = 0; rr < 8; rr++) {
                    int r = wi * 8 + rr;
                    float v0 = sm[OFF_S + r * PS + l];
                    float v1 = sm[OFF_S + r * PS + 32 + l];
                    float mx = fmaxf(v0, v1);
                    #pragma unroll
                    for (int o = 16; o > 0; o >>= 1)
                        mx = fmaxf(mx, __shfl_xor_sync(0xffffffffu, mx, o));
                    float e0 = __expf(v0 - mx), e1 = __expf(v1 - mx);
                    float s = e0 + e1;
                    #pragma unroll
                    for (int o = 16; o > 0; o >>= 1)
                        s += __shfl_xor_sync(0xffffffffu, s, o);
                    float inv = 1.0f / s;
                    sm[OFF_S + r * PS + l]      = e0 * inv;
                    sm[OFF_S + r * PS + 32 + l] = e1 * inv;
                }
            }
            __syncwarp();

            // ---- O = P V  (warp-local P rows) -> A region at col h32 ----
            {
                u64 acc[4];
                #pragma unroll
                for (int i = 0; i < 4; ++i) acc[i] = 0;
                #pragma unroll 4
                for (int m = 0; m < 64; ++m) {
                    float p = sm[OFF_S + pvrow * PS + m];
                    u64 pp = pk2(p, p);
                    v4u v0, v1;
                    v0.f = *reinterpret_cast<const float4*>(
                        &sm[OFF_V + m * PA + h32 + pvd0]);
                    v1.f = *reinterpret_cast<const float4*>(
                        &sm[OFF_V + m * PA + h32 + pvd0 + 4]);
                    fma2(acc[0], pp, v0.u[0]); fma2(acc[1], pp, v0.u[1]);
                    fma2(acc[2], pp, v1.u[0]); fma2(acc[3], pp, v1.u[1]);
                }
                #pragma unroll
                for (int i = 0; i < 4; ++i)
                    *reinterpret_cast<u64*>(
                        &sm[OFF_A + pvrow * PA + h32 + pvd0 + 2 * i]) = acc[i];
            }
            __syncwarp();   // own S rows reusable next head
        }  // heads

        __syncthreads();    // all warps' O complete before merge1 reads A

        // ---- merge1: M += O_all @ W1_branch^T (one wide GEMM, red=192) ----
        wide_gemm<2>(sm, OFF_A, merge1_w + br * 192, 384, nullptr, 1.f,
                     nullptr, nullptr, M, t);
        // ends with a full barrier (last chunk sync) -> safe to overwrite A
    }  // branches

    // ---- leaky relu(M) -> A (dead) ----
    #pragma unroll
    for (int half = 0; half < 2; ++half)
        #pragma unroll
        for (int j = 0; j < 3; ++j)
            #pragma unroll
            for (int i = 0; i < 8; ++i) {
                float v = M[i][half * 3 + j];
                v = v > 0.f ? v : 0.2f * v;
                sm[OFF_A + (n0 + i) * PA + half * 96 + tc * 3 + j] = v;
            }
    // merge2: T = relu(M) @ W2^T + b2 -> Q region
    wide_gemm<0>(sm, OFF_A, merge2_w, 192, merge2_b, 1.f, sm + OFF_Q, nullptr, nullptr, t);
    // proj: out = T @ Wp^T + pb -> global
    wide_gemm<1>(sm, OFF_Q, proj_w, 192, proj_b, 1.f, nullptr,
                 out + (size_t)w * 12288, nullptr, t);
}

extern "C" void kernel_launch(void* const* d_in, const int* in_sizes, int n_in,
                              void* d_out, int out_size) {
    const float* x        = (const float*)d_in[0];
    const float* y        = (const float*)d_in[1];
    const float* mask_x   = (const float*)d_in[2];
    const float* mask_y   = (const float*)d_in[3];
    const float* qkv_w    = (const float*)d_in[4];
    const float* qkv_b    = (const float*)d_in[5];
    const float* kv_w     = (const float*)d_in[6];
    const float* kv_b     = (const float*)d_in[7];
    const float* rpb_x    = (const float*)d_in[8];
    const float* rpb_y    = (const float*)d_in[9];
    const float* merge1_w = (const float*)d_in[10];
    const float* merge1_b = (const float*)d_in[11];
    const float* merge2_w = (const float*)d_in[12];
    const float* merge2_b = (const float*)d_in[13];
    const float* proj_w   = (const float*)d_in[14];
    const float* proj_b   = (const float*)d_in[15];
    const int*   rel_idx  = (const int*)d_in[16];
    float* out = (float*)d_out;

    cudaFuncSetAttribute(fused_attn_kernel,
                         cudaFuncAttributeMaxDynamicSharedMemorySize,
                         SMEM_FLOATS * 4);

    bias_pre_kernel<<<192, 256>>>(rpb_x, rpb_y, rel_idx);
    fused_attn_kernel<<<2048, NT, SMEM_FLOATS * 4>>>(
        x, y, mask_x, mask_y, qkv_w, qkv_b, kv_w, kv_b,
        merge1_w, merge1_b, merge2_w, merge2_b, proj_w, proj_b, out);
}

// round 14
// speedup vs baseline: 1.5331x; 1.5318x over previous
#include <cuda_runtime.h>

#define NT 256
#define PA 196            // pitch for A, Q, V (196 % 32 == 4 -> conflict-free frags)
#define PKT 64            // Kt pitch [d][m]
#define PS 66             // S pitch
#define PW 20             // W stage pitch (16-col chunks; 20*gid+tig bijective mod 32)

#define OFF_A   0         // 64 x PA : X/Y (tf32), per-head O (tf32), relu(M) (tf32)
#define OFF_Q   12544     // 64 x PA : scaled Q (fp32), later merge2 out T (tf32)
#define OFF_KT  25088     // 192 x PKT : K transposed (fp32, per branch)
#define OFF_V   37376     // 64 x PA : full V (fp32, per branch)
#define OFF_S   49920     // 64 x PS (also W stage buffer 1 during GEMMs)
#define OFF_W0  54144     // 192 x PW = 3840
#define OFF_W1  OFF_S
#define SMEM_FLOATS 57984 // 231936 bytes

typedef unsigned long long u64;
typedef union { float4 f; u64 u[2]; } v4u;

static __device__ __forceinline__ u64 pk2(float lo, float hi) {
    u64 r; asm("mov.b64 %0,{%1,%2};" : "=l"(r) : "f"(lo), "f"(hi)); return r;
}
static __device__ __forceinline__ void upk2(u64 v, float& lo, float& hi) {
    asm("mov.b64 {%0,%1}, %2;" : "=f"(lo), "=f"(hi) : "l"(v));
}
static __device__ __forceinline__ void fma2(u64& d, u64 a, u64 b) {
    asm("fma.rn.f32x2 %0, %1, %2, %0;" : "+l"(d) : "l"(a), "l"(b));
}
static __device__ __forceinline__ unsigned cvt_tf32(float f) {
    unsigned u; asm("cvt.rna.tf32.f32 %0, %1;" : "=r"(u) : "f"(f)); return u;
}
static __device__ __forceinline__ float tf32f(float f) {
    return __uint_as_float(cvt_tf32(f));
}
// D(16x8,f32) += A(16x8,row,tf32) * B(8x8 KxN, col, tf32)
static __device__ __forceinline__ void mma8(float* d, unsigned a0, unsigned a1,
                                            unsigned a2, unsigned a3,
                                            unsigned b0, unsigned b1) {
    asm("mma.sync.aligned.m16n8k8.row.col.f32.tf32.tf32.f32 "
        "{%0,%1,%2,%3}, {%4,%5,%6,%7}, {%8,%9}, {%0,%1,%2,%3};"
        : "+f"(d[0]), "+f"(d[1]), "+f"(d[2]), "+f"(d[3])
        : "r"(a0), "r"(a1), "r"(a2), "r"(a3), "r"(b0), "r"(b1));
}

__device__ float g_bias[2 * 6 * 64 * 64];

__global__ void bias_pre_kernel(const float* __restrict__ rpb_x,
                                const float* __restrict__ rpb_y,
                                const int* __restrict__ rel_idx) {
    int i = blockIdx.x * blockDim.x + threadIdx.x;
    if (i >= 2 * 6 * 4096) return;
    int br = i / (6 * 4096);
    int h  = (i / 4096) % 6;
    int nm = i & 4095;
    const float* tab = br ? rpb_y : rpb_x;
    g_bias[i] = tab[rel_idx[nm] * 6 + h];
}

// 64x192 GEMM via mma.sync tf32: dst[n][o] = (sum_c src[n][c]*W[o][c] + b)*scl.
// src in SMEM pitch PA (tf32-rounded). W row-major [o][ldw], staged per 16-col
// k-chunk (double-buffered, register prefetch, cvt.rna at stage).
// Warp grid 4x2: warp wr rows 16wr..+15, warp wc cols 96wc..+95.
// DST: 0 -> SMEM pitch PA, 1 -> global pitch 192, 2 -> accumulate into M (mma
// layout, no bias/scale), 3 -> SMEM transposed Kt[o][n] pitch PKT.
template<int DST, bool CVT>
static __device__ __forceinline__ void mma_gemm(
    float* sm, int srcOff, const float* __restrict__ Wg, int ldw,
    const float* __restrict__ bg, float scl,
    float* dstS, float* __restrict__ dstG, float* M, int t)
{
    const int lane = t & 31, wid = t >> 5;
    const int gid = lane >> 2, tig = lane & 3;
    const int r0 = (wid >> 1) * 16 + gid;     // output row (and +8)
    const int n0 = (wid & 1) * 96;            // output col base

    int wgo[3], sso[3];
    #pragma unroll
    for (int k = 0; k < 3; ++k) {
        int e = k * NT + t;                   // 0..767 -> 192 rows x 4 float4
        int o = e >> 2, c4 = e & 3;
        wgo[k] = o * ldw + c4 * 4;
        sso[k] = o * PW + c4 * 4;
    }

    float dl[48];
    float* d = (DST == 2) ? M : dl;
    if (DST != 2) {
        #pragma unroll
        for (int i = 0; i < 48; ++i) dl[i] = 0.f;
    }

    float4 pre[3];
    #pragma unroll
    for (int k = 0; k < 3; ++k)
        pre[k] = *reinterpret_cast<const float4*>(&Wg[wgo[k]]);
    #pragma unroll
    for (int k = 0; k < 3; ++k) {
        float4 c;
        c.x = tf32f(pre[k].x); c.y = tf32f(pre[k].y);
        c.z = tf32f(pre[k].z); c.w = tf32f(pre[k].w);
        *reinterpret_cast<float4*>(&sm[OFF_W0 + sso[k]]) = c;
    }
    __syncthreads();

    #pragma unroll 1
    for (int ch = 0; ch < 12; ++ch) {
        if (ch < 11) {
            #pragma unroll
            for (int k = 0; k < 3; ++k)
                pre[k] = *reinterpret_cast<const float4*>(
                    &Wg[wgo[k] + (ch + 1) * 16]);
        }
        const float* wb = sm + ((ch & 1) ? OFF_W1 : OFF_W0);
        const float* sa = sm + srcOff + ch * 16;
        #pragma unroll
        for (int ks = 0; ks < 2; ++ks) {
            const int k0 = ks * 8;
            unsigned a0 = __float_as_uint(sa[r0 * PA + k0 + tig]);
            unsigned a1 = __float_as_uint(sa[(r0 + 8) * PA + k0 + tig]);
            unsigned a2 = __float_as_uint(sa[r0 * PA + k0 + tig + 4]);
            unsigned a3 = __float_as_uint(sa[(r0 + 8) * PA + k0 + tig + 4]);
            #pragma unroll
            for (int j = 0; j < 12; ++j) {
                const float* wr_ = &wb[(n0 + 8 * j + gid) * PW + k0 + tig];
                unsigned b0 = __float_as_uint(wr_[0]);
                unsigned b1 = __float_as_uint(wr_[4]);
                mma8(d + j * 4, a0, a1, a2, a3, b0, b1);
            }
        }
        if (ch < 11) {
            float* nb = sm + ((ch & 1) ? OFF_W0 : OFF_W1);
            #pragma unroll
            for (int k = 0; k < 3; ++k) {
                float4 c;
                c.x = tf32f(pre[k].x); c.y = tf32f(pre[k].y);
                c.z = tf32f(pre[k].z); c.w = tf32f(pre[k].w);
                *reinterpret_cast<float4*>(&nb[sso[k]]) = c;
            }
        }
        __syncthreads();
    }

    if (DST != 2) {
        #pragma unroll
        for (int j = 0; j < 12; ++j) {
            const int o = n0 + 8 * j + 2 * tig;
            float b0 = bg[o], b1 = bg[o + 1];
            float v00 = (d[j*4+0] + b0) * scl, v01 = (d[j*4+1] + b1) * scl;
            float v10 = (d[j*4+2] + b0) * scl, v11 = (d[j*4+3] + b1) * scl;
            if (CVT) {
                v00 = tf32f(v00); v01 = tf32f(v01);
                v10 = tf32f(v10); v11 = tf32f(v11);
            }
            if (DST == 3) {
                dstS[(o    ) * PKT + r0]     = v00;
                dstS[(o + 1) * PKT + r0]     = v01;
                dstS[(o    ) * PKT + r0 + 8] = v10;
                dstS[(o + 1) * PKT + r0 + 8] = v11;
            } else if (DST == 1) {
                *reinterpret_cast<u64*>(&dstG[r0 * 192 + o])       = pk2(v00, v01);
                *reinterpret_cast<u64*>(&dstG[(r0 + 8) * 192 + o]) = pk2(v10, v11);
            } else {
                *reinterpret_cast<u64*>(&dstS[r0 * PA + o])        = pk2(v00, v01);
                *reinterpret_cast<u64*>(&dstS[(r0 + 8) * PA + o])  = pk2(v10, v11);
            }
        }
    }
}

__global__ void __launch_bounds__(NT, 1) fused_attn_kernel(
    const float* __restrict__ x, const float* __restrict__ y,
    const float* __restrict__ mask_x, const float* __restrict__ mask_y,
    const float* __restrict__ qkv_w, const float* __restrict__ qkv_b,
    const float* __restrict__ kv_w, const float* __restrict__ kv_b,
    const float* __restrict__ merge1_w, const float* __restrict__ merge1_b,
    const float* __restrict__ merge2_w, const float* __restrict__ merge2_b,
    const float* __restrict__ proj_w, const float* __restrict__ proj_b,
    float* __restrict__ out)
{
    extern __shared__ float sm[];
    const int t = threadIdx.x;
    const int w = blockIdx.x;
    const float scale = 0.17677669529663687f;  // 32^-0.5

    // mma output mapping (also M layout)
    const int lane = t & 31, wid = t >> 5;
    const int gid = lane >> 2, tig = lane & 3;
    const int r0 = (wid >> 1) * 16 + gid;
    const int n0 = (wid & 1) * 96;

    // merge1 accumulator in mma D layout: M[j*4+c]
    float M[48];
    #pragma unroll
    for (int j = 0; j < 12; ++j) {
        float b0 = merge1_b[n0 + 8 * j + 2 * tig];
        float b1 = merge1_b[n0 + 8 * j + 2 * tig + 1];
        M[j*4+0] = b0; M[j*4+1] = b1; M[j*4+2] = b0; M[j*4+3] = b1;
    }

    // attention-phase mappings (warp-local: warp wi owns rows 8wi..8wi+7)
    const int sr0 = (t >> 4) * 4;            // S: 4 rows
    const int sm0 = (t & 15) * 4;            // S: 4 m-cols
    const int pvrow = (t >> 5) * 8 + ((t & 31) >> 2);  // PV: 1 row
    const int pvd0  = (t & 3) * 8;                     // PV: 8 d-cols

    #pragma unroll 1
    for (int br = 0; br < 2; ++br) {
        // ---- load activation (X or Y) into A, tf32-rounded ----
        {
            const float* ap = (br ? y : x) + (size_t)w * 12288;
            for (int i = t; i < 12288; i += NT) {
                int n = i / 192, c = i - n * 192;
                sm[OFF_A + n * PA + c] = tf32f(ap[i]);
            }
        }
        // mma_gemm's prologue sync orders the A stores before reads.
        if (br == 0) {
            mma_gemm<0,false>(sm, OFF_A, qkv_w,             192, qkv_b,       scale, sm + OFF_Q,  nullptr, nullptr, t);
            mma_gemm<3,false>(sm, OFF_A, qkv_w + 192 * 192, 192, qkv_b + 192, 1.f,   sm + OFF_KT, nullptr, nullptr, t);
            mma_gemm<0,false>(sm, OFF_A, qkv_w + 384 * 192, 192, qkv_b + 384, 1.f,   sm + OFF_V,  nullptr, nullptr, t);
        } else {
            mma_gemm<3,false>(sm, OFF_A, kv_w,              192, kv_b,        1.f,   sm + OFF_KT, nullptr, nullptr, t);
            mma_gemm<0,false>(sm, OFF_A, kv_w + 192 * 192,  192, kv_b + 192,  1.f,   sm + OFF_V,  nullptr, nullptr, t);
        }
        __syncthreads();   // Q/Kt/V epilogue stores -> visible to attention

        const float* bias_base = g_bias + (size_t)(br * 6) * 4096;
        const float* maskp = (br ? mask_y : mask_x) + (size_t)(w & 1023) * 4096;

        float4 mk4[4];
        #pragma unroll
        for (int i = 0; i < 4; ++i)
            mk4[i] = *reinterpret_cast<const float4*>(&maskp[(sr0 + i) * 64 + sm0]);

        #pragma unroll 1
        for (int h = 0; h < 6; ++h) {
            const int h32 = h * 32;

            // ---- S = Q Kt + bias + mask  (fp32 scalar, fma2 over m) ----
            {
                float4 bi4[4];
                const float* bb = bias_base + h * 4096;
                #pragma unroll
                for (int i = 0; i < 4; ++i)
                    bi4[i] = *reinterpret_cast<const float4*>(&bb[(sr0 + i) * 64 + sm0]);
                u64 acc[4][2];
                #pragma unroll
                for (int i = 0; i < 4; ++i) { acc[i][0] = 0; acc[i][1] = 0; }
                #pragma unroll 8
                for (int d = 0; d < 32; ++d) {
                    v4u kt;
                    kt.f = *reinterpret_cast<const float4*>(
                        &sm[OFF_KT + (h32 + d) * PKT + sm0]);
                    #pragma unroll
                    for (int i = 0; i < 4; ++i) {
                        float q = sm[OFF_Q + (sr0 + i) * PA + h32 + d];
                        u64 qq = pk2(q, q);
                        fma2(acc[i][0], qq, kt.u[0]);
                        fma2(acc[i][1], qq, kt.u[1]);
                    }
                }
                #pragma unroll
                for (int i = 0; i < 4; ++i) {
                    float s0, s1, s2, s3;
                    upk2(acc[i][0], s0, s1); upk2(acc[i][1], s2, s3);
                    s0 += bi4[i].x + mk4[i].x;  s1 += bi4[i].y + mk4[i].y;
                    s2 += bi4[i].z + mk4[i].z;  s3 += bi4[i].w + mk4[i].w;
                    *reinterpret_cast<u64*>(&sm[OFF_S + (sr0 + i) * PS + sm0])     = pk2(s0, s1);
                    *reinterpret_cast<u64*>(&sm[OFF_S + (sr0 + i) * PS + sm0 + 2]) = pk2(s2, s3);
                }
            }
            __syncwarp();

            // ---- softmax: warp wi owns rows 8wi..8wi+7 ----
            {
                const int wi = t >> 5, l = t & 31;
                #pragma unroll
                for (int rr = 0; rr < 8; rr++) {
                    int r = wi * 8 + rr;
                    float v0 = sm[OFF_S + r * PS + l];
                    float v1 = sm[OFF_S + r * PS + 32 + l];
                    float mx = fmaxf(v0, v1);
                    #pragma unroll
                    for (int o = 16; o > 0; o >>= 1)
                        mx = fmaxf(mx, __shfl_xor_sync(0xffffffffu, mx, o));
                    float e0 = __expf(v0 - mx), e1 = __expf(v1 - mx);
                    float s = e0 + e1;
                    #pragma unroll
                    for (int o = 16; o > 0; o >>= 1)
                        s += __shfl_xor_sync(0xffffffffu, s, o);
                    float inv = 1.0f / s;
                    sm[OFF_S + r * PS + l]      = e0 * inv;
                    sm[OFF_S + r * PS + 32 + l] = e1 * inv;
                }
            }
            __syncwarp();

            // ---- O = P V (warp-local rows) -> A at col h32, tf32-rounded ----
            {
                u64 acc[4];
                #pragma unroll
                for (int i = 0; i < 4; ++i) acc[i] = 0;
                #pragma unroll 4
                for (int m = 0; m < 64; ++m) {
                    float p = sm[OFF_S + pvrow * PS + m];
                    u64 pp = pk2(p, p);
                    v4u v0, v1;
                    v0.f = *reinterpret_cast<const float4*>(
                        &sm[OFF_V + m * PA + h32 + pvd0]);
                    v1.f = *reinterpret_cast<const float4*>(
                        &sm[OFF_V + m * PA + h32 + pvd0 + 4]);
                    fma2(acc[0], pp, v0.u[0]); fma2(acc[1], pp, v0.u[1]);
                    fma2(acc[2], pp, v1.u[0]); fma2(acc[3], pp, v1.u[1]);
                }
                #pragma unroll
                for (int i = 0; i < 4; ++i) {
                    float lo, hi; upk2(acc[i], lo, hi);
                    *reinterpret_cast<u64*>(
                        &sm[OFF_A + pvrow * PA + h32 + pvd0 + 2 * i]) =
                        pk2(tf32f(lo), tf32f(hi));
                }
            }
            __syncwarp();
        }  // heads

        __syncthreads();    // all warps' O complete before merge1 reads A

        // ---- merge1: M += O_all @ W1_branch^T (mma, accumulate in M) ----
        mma_gemm<2,false>(sm, OFF_A, merge1_w + br * 192, 384, nullptr, 1.f,
                          nullptr, nullptr, M, t);
        // ends with a full barrier -> safe to overwrite A next branch
    }  // branches

    // ---- leaky relu(M) -> A (dead), tf32-rounded for merge2 ----
    #pragma unroll
    for (int j = 0; j < 12; ++j) {
        const int o = n0 + 8 * j + 2 * tig;
        float v00 = M[j*4+0], v01 = M[j*4+1], v10 = M[j*4+2], v11 = M[j*4+3];
        v00 = v00 > 0.f ? v00 : 0.2f * v00;
        v01 = v01 > 0.f ? v01 : 0.2f * v01;
        v10 = v10 > 0.f ? v10 : 0.2f * v10;
        v11 = v11 > 0.f ? v11 : 0.2f * v11;
        *reinterpret_cast<u64*>(&sm[OFF_A + r0 * PA + o]) =
            pk2(tf32f(v00), tf32f(v01));
        *reinterpret_cast<u64*>(&sm[OFF_A + (r0 + 8) * PA + o]) =
            pk2(tf32f(v10), tf32f(v11));
    }
    // merge2: T = relu(M) @ W2^T + b2 -> Q region (tf32-rounded: feeds proj)
    mma_gemm<0,true>(sm, OFF_A, merge2_w, 192, merge2_b, 1.f, sm + OFF_Q,
                     nullptr, nullptr, t);
    // proj: out = T @ Wp^T + pb -> global
    mma_gemm<1,false>(sm, OFF_Q, proj_w, 192, proj_b, 1.f, nullptr,
                      out + (size_t)w * 12288, nullptr, t);
}

extern "C" void kernel_launch(void* const* d_in, const int* in_sizes, int n_in,
                              void* d_out, int out_size) {
    const float* x        = (const float*)d_in[0];
    const float* y        = (const float*)d_in[1];
    const float* mask_x   = (const float*)d_in[2];
    const float* mask_y   = (const float*)d_in[3];
    const float* qkv_w    = (const float*)d_in[4];
    const float* qkv_b    = (const float*)d_in[5];
    const float* kv_w     = (const float*)d_in[6];
    const float* kv_b     = (const float*)d_in[7];
    const float* rpb_x    = (const float*)d_in[8];
    const float* rpb_y    = (const float*)d_in[9];
    const float* merge1_w = (const float*)d_in[10];
    const float* merge1_b = (const float*)d_in[11];
    const float* merge2_w = (const float*)d_in[12];
    const float* merge2_b = (const float*)d_in[13];
    const float* proj_w   = (const float*)d_in[14];
    const float* proj_b   = (const float*)d_in[15];
    const int*   rel_idx  = (const int*)d_in[16];
    float* out = (float*)d_out;

    cudaFuncSetAttribute(fused_attn_kernel,
                         cudaFuncAttributeMaxDynamicSharedMemorySize,
                         SMEM_FLOATS * 4);

    bias_pre_kernel<<<192, 256>>>(rpb_x, rpb_y, rel_idx);
    fused_attn_kernel<<<2048, NT, SMEM_FLOATS * 4>>>(
        x, y, mask_x, mask_y, qkv_w, qkv_b, kv_w, kv_b,
        merge1_w, merge1_b, merge2_w, merge2_b, proj_w, proj_b, out);
}

// round 15
// speedup vs baseline: 1.6973x; 1.1071x over previous
#include <cuda_runtime.h>

#define NT 256
#define PA 196            // pitch for A, Q, V (196 % 32 == 4 -> conflict-free frags)
#define PKT 64            // Kt pitch [d][m]
#define PS 66             // S pitch
#define PW 20             // W stage pitch (16-col chunks)

#define OFF_A   0         // 64 x PA : X/Y (tf32), per-head O (tf32), relu(M) (tf32)
#define OFF_Q   12544     // 64 x PA : scaled Q (tf32), later merge2 out T (tf32)
#define OFF_KT  25088     // 192 x PKT : K transposed (tf32, per branch)
#define OFF_V   37376     // 64 x PA : full V (tf32, per branch)
#define OFF_S   49920     // 64 x PS (also W stage buffer 1 during GEMMs)
#define OFF_W0  54144     // 192 x PW = 3840
#define OFF_W1  OFF_S
#define SMEM_FLOATS 57984 // 231936 bytes

typedef unsigned long long u64;

static __device__ __forceinline__ u64 pk2(float lo, float hi) {
    u64 r; asm("mov.b64 %0,{%1,%2};" : "=l"(r) : "f"(lo), "f"(hi)); return r;
}
static __device__ __forceinline__ unsigned cvt_tf32(float f) {
    unsigned u; asm("cvt.rna.tf32.f32 %0, %1;" : "=r"(u) : "f"(f)); return u;
}
static __device__ __forceinline__ float tf32f(float f) {
    return __uint_as_float(cvt_tf32(f));
}
// D(16x8,f32) += A(16x8,row,tf32) * B(8x8 KxN, col, tf32)
static __device__ __forceinline__ void mma8(float* d, unsigned a0, unsigned a1,
                                            unsigned a2, unsigned a3,
                                            unsigned b0, unsigned b1) {
    asm("mma.sync.aligned.m16n8k8.row.col.f32.tf32.tf32.f32 "
        "{%0,%1,%2,%3}, {%4,%5,%6,%7}, {%8,%9}, {%0,%1,%2,%3};"
        : "+f"(d[0]), "+f"(d[1]), "+f"(d[2]), "+f"(d[3])
        : "r"(a0), "r"(a1), "r"(a2), "r"(a3), "r"(b0), "r"(b1));
}
static __device__ __forceinline__ void barpair(int id) {
    asm volatile("bar.sync %0, 64;" :: "r"(id) : "memory");
}
static __device__ __forceinline__ unsigned lds_u(const float* p) {
    return __float_as_uint(*p);
}

__device__ float g_bias[2 * 6 * 64 * 64];

__global__ void bias_pre_kernel(const float* __restrict__ rpb_x,
                                const float* __restrict__ rpb_y,
                                const int* __restrict__ rel_idx) {
    int i = blockIdx.x * blockDim.x + threadIdx.x;
    if (i >= 2 * 6 * 4096) return;
    int br = i / (6 * 4096);
    int h  = (i / 4096) % 6;
    int nm = i & 4095;
    const float* tab = br ? rpb_y : rpb_x;
    g_bias[i] = tab[rel_idx[nm] * 6 + h];
}

// 64x192 GEMM via mma.sync tf32 (see R14). DST: 0 -> SMEM pitch PA,
// 1 -> global pitch 192, 2 -> accumulate into M, 3 -> SMEM transposed pitch PKT.
template<int DST, bool CVT>
static __device__ __forceinline__ void mma_gemm(
    float* sm, int srcOff, const float* __restrict__ Wg, int ldw,
    const float* __restrict__ bg, float scl,
    float* dstS, float* __restrict__ dstG, float* M, int t)
{
    const int lane = t & 31, wid = t >> 5;
    const int gid = lane >> 2, tig = lane & 3;
    const int r0 = (wid >> 1) * 16 + gid;
    const int n0 = (wid & 1) * 96;

    int wgo[3], sso[3];
    #pragma unroll
    for (int k = 0; k < 3; ++k) {
        int e = k * NT + t;
        int o = e >> 2, c4 = e & 3;
        wgo[k] = o * ldw + c4 * 4;
        sso[k] = o * PW + c4 * 4;
    }

    float dl[48];
    float* d = (DST == 2) ? M : dl;
    if (DST != 2) {
        #pragma unroll
        for (int i = 0; i < 48; ++i) dl[i] = 0.f;
    }

    float4 pre[3];
    #pragma unroll
    for (int k = 0; k < 3; ++k)
        pre[k] = *reinterpret_cast<const float4*>(&Wg[wgo[k]]);
    #pragma unroll
    for (int k = 0; k < 3; ++k) {
        float4 c;
        c.x = tf32f(pre[k].x); c.y = tf32f(pre[k].y);
        c.z = tf32f(pre[k].z); c.w = tf32f(pre[k].w);
        *reinterpret_cast<float4*>(&sm[OFF_W0 + sso[k]]) = c;
    }
    __syncthreads();

    #pragma unroll 1
    for (int ch = 0; ch < 12; ++ch) {
        if (ch < 11) {
            #pragma unroll
            for (int k = 0; k < 3; ++k)
                pre[k] = *reinterpret_cast<const float4*>(
                    &Wg[wgo[k] + (ch + 1) * 16]);
        }
        const float* wb = sm + ((ch & 1) ? OFF_W1 : OFF_W0);
        const float* sa = sm + srcOff + ch * 16;
        #pragma unroll
        for (int ks = 0; ks < 2; ++ks) {
            const int k0 = ks * 8;
            unsigned a0 = lds_u(&sa[r0 * PA + k0 + tig]);
            unsigned a1 = lds_u(&sa[(r0 + 8) * PA + k0 + tig]);
            unsigned a2 = lds_u(&sa[r0 * PA + k0 + tig + 4]);
            unsigned a3 = lds_u(&sa[(r0 + 8) * PA + k0 + tig + 4]);
            #pragma unroll
            for (int j = 0; j < 12; ++j) {
                const float* wr_ = &wb[(n0 + 8 * j + gid) * PW + k0 + tig];
                mma8(d + j * 4, a0, a1, a2, a3, lds_u(wr_), lds_u(wr_ + 4));
            }
        }
        if (ch < 11) {
            float* nb = sm + ((ch & 1) ? OFF_W0 : OFF_W1);
            #pragma unroll
            for (int k = 0; k < 3; ++k) {
                float4 c;
                c.x = tf32f(pre[k].x); c.y = tf32f(pre[k].y);
                c.z = tf32f(pre[k].z); c.w = tf32f(pre[k].w);
                *reinterpret_cast<float4*>(&nb[sso[k]]) = c;
            }
        }
        __syncthreads();
    }

    if (DST != 2) {
        #pragma unroll
        for (int j = 0; j < 12; ++j) {
            const int o = n0 + 8 * j + 2 * tig;
            float b0 = bg[o], b1 = bg[o + 1];
            float v00 = (d[j*4+0] + b0) * scl, v01 = (d[j*4+1] + b1) * scl;
            float v10 = (d[j*4+2] + b0) * scl, v11 = (d[j*4+3] + b1) * scl;
            if (CVT) {
                v00 = tf32f(v00); v01 = tf32f(v01);
                v10 = tf32f(v10); v11 = tf32f(v11);
            }
            if (DST == 3) {
                dstS[(o    ) * PKT + r0]     = v00;
                dstS[(o + 1) * PKT + r0]     = v01;
                dstS[(o    ) * PKT + r0 + 8] = v10;
                dstS[(o + 1) * PKT + r0 + 8] = v11;
            } else if (DST == 1) {
                *reinterpret_cast<u64*>(&dstG[r0 * 192 + o])       = pk2(v00, v01);
                *reinterpret_cast<u64*>(&dstG[(r0 + 8) * 192 + o]) = pk2(v10, v11);
            } else {
                *reinterpret_cast<u64*>(&dstS[r0 * PA + o])        = pk2(v00, v01);
                *reinterpret_cast<u64*>(&dstS[(r0 + 8) * PA + o])  = pk2(v10, v11);
            }
        }
    }
}

__global__ void __launch_bounds__(NT, 1) fused_attn_kernel(
    const float* __restrict__ x, const float* __restrict__ y,
    const float* __restrict__ mask_x, const float* __restrict__ mask_y,
    const float* __restrict__ qkv_w, const float* __restrict__ qkv_b,
    const float* __restrict__ kv_w, const float* __restrict__ kv_b,
    const float* __restrict__ merge1_w, const float* __restrict__ merge1_b,
    const float* __restrict__ merge2_w, const float* __restrict__ merge2_b,
    const float* __restrict__ proj_w, const float* __restrict__ proj_b,
    float* __restrict__ out)
{
    extern __shared__ float sm[];
    const int t = threadIdx.x;
    const int w = blockIdx.x;
    const float scale = 0.17677669529663687f;  // 32^-0.5

    const int lane = t & 31, wid = t >> 5;
    const int gid = lane >> 2, tig = lane & 3;
    const int r0 = (wid >> 1) * 16 + gid;      // mma-gemm row mapping
    const int n0 = (wid & 1) * 96;

    // attention mappings: warp pair (wid>>1) owns rows pr0..pr0+15
    const int pr0 = (wid >> 1) * 16;
    const int swc = wid & 1;                   // col-half selector
    const int barid = 1 + (wid >> 1);

    // merge1 accumulator in mma D layout
    float M[48];
    #pragma unroll
    for (int j = 0; j < 12; ++j) {
        float b0 = merge1_b[n0 + 8 * j + 2 * tig];
        float b1 = merge1_b[n0 + 8 * j + 2 * tig + 1];
        M[j*4+0] = b0; M[j*4+1] = b1; M[j*4+2] = b0; M[j*4+3] = b1;
    }

    #pragma unroll 1
    for (int br = 0; br < 2; ++br) {
        // ---- load activation (X or Y) into A, tf32-rounded ----
        {
            const float* ap = (br ? y : x) + (size_t)w * 12288;
            for (int i = t; i < 12288; i += NT) {
                int n = i / 192, c = i - n * 192;
                sm[OFF_A + n * PA + c] = tf32f(ap[i]);
            }
        }
        if (br == 0) {
            mma_gemm<0,true>(sm, OFF_A, qkv_w,             192, qkv_b,       scale, sm + OFF_Q,  nullptr, nullptr, t);
            mma_gemm<3,true>(sm, OFF_A, qkv_w + 192 * 192, 192, qkv_b + 192, 1.f,   sm + OFF_KT, nullptr, nullptr, t);
            mma_gemm<0,true>(sm, OFF_A, qkv_w + 384 * 192, 192, qkv_b + 384, 1.f,   sm + OFF_V,  nullptr, nullptr, t);
        } else {
            mma_gemm<3,true>(sm, OFF_A, kv_w,              192, kv_b,        1.f,   sm + OFF_KT, nullptr, nullptr, t);
            mma_gemm<0,true>(sm, OFF_A, kv_w + 192 * 192,  192, kv_b + 192,  1.f,   sm + OFF_V,  nullptr, nullptr, t);
        }
        __syncthreads();   // Q/Kt/V epilogue stores -> visible to attention

        const float* bias_base = g_bias + (size_t)(br * 6) * 4096;
        const float* maskp = (br ? mask_y : mask_x) + (size_t)(w & 1023) * 4096;

        // mask is head-invariant: hoist in S-epilogue (mma D) layout
        float mk[4][4];
        #pragma unroll
        for (int j = 0; j < 4; ++j) {
            const int col = swc * 32 + 8 * j + 2 * tig;
            float2 a = *reinterpret_cast<const float2*>(&maskp[(pr0 + gid) * 64 + col]);
            float2 b = *reinterpret_cast<const float2*>(&maskp[(pr0 + 8 + gid) * 64 + col]);
            mk[j][0] = a.x; mk[j][1] = a.y; mk[j][2] = b.x; mk[j][3] = b.y;
        }

        #pragma unroll 1
        for (int h = 0; h < 6; ++h) {
            const int h32 = h * 32;

            // ---- S = Q Kt (mma tf32), + bias + mask in fp32 epilogue ----
            {
                float sacc[16];
                #pragma unroll
                for (int i = 0; i < 16; ++i) sacc[i] = 0.f;
                #pragma unroll
                for (int ks = 0; ks < 4; ++ks) {
                    const int k0 = 8 * ks;
                    unsigned a0 = lds_u(&sm[OFF_Q + (pr0 + gid) * PA + h32 + k0 + tig]);
                    unsigned a1 = lds_u(&sm[OFF_Q + (pr0 + 8 + gid) * PA + h32 + k0 + tig]);
                    unsigned a2 = lds_u(&sm[OFF_Q + (pr0 + gid) * PA + h32 + k0 + tig + 4]);
                    unsigned a3 = lds_u(&sm[OFF_Q + (pr0 + 8 + gid) * PA + h32 + k0 + tig + 4]);
                    #pragma unroll
                    for (int j = 0; j < 4; ++j) {
                        const int nn = swc * 32 + 8 * j + gid;
                        unsigned b0 = lds_u(&sm[OFF_KT + (h32 + k0 + tig) * PKT + nn]);
                        unsigned b1 = lds_u(&sm[OFF_KT + (h32 + k0 + tig + 4) * PKT + nn]);
                        mma8(sacc + j * 4, a0, a1, a2, a3, b0, b1);
                    }
                }
                const float* bb = bias_base + h * 4096;
                #pragma unroll
                for (int j = 0; j < 4; ++j) {
                    const int col = swc * 32 + 8 * j + 2 * tig;
                    float2 ba = *reinterpret_cast<const float2*>(&bb[(pr0 + gid) * 64 + col]);
                    float2 bbb = *reinterpret_cast<const float2*>(&bb[(pr0 + 8 + gid) * 64 + col]);
                    float s0 = sacc[j*4+0] + ba.x + mk[j][0];
                    float s1 = sacc[j*4+1] + ba.y + mk[j][1];
                    float s2 = sacc[j*4+2] + bbb.x + mk[j][2];
                    float s3 = sacc[j*4+3] + bbb.y + mk[j][3];
                    *reinterpret_cast<u64*>(&sm[OFF_S + (pr0 + gid) * PS + col])     = pk2(s0, s1);
                    *reinterpret_cast<u64*>(&sm[OFF_S + (pr0 + 8 + gid) * PS + col]) = pk2(s2, s3);
                }
            }
            barpair(barid);

            // ---- softmax (fp32): warp handles 8 of the pair's 16 rows ----
            {
                const int l = lane;
                #pragma unroll
                for (int rr = 0; rr < 8; rr++) {
                    int r = pr0 + swc * 8 + rr;
                    float v0 = sm[OFF_S + r * PS + l];
                    float v1 = sm[OFF_S + r * PS + 32 + l];
                    float mx = fmaxf(v0, v1);
                    #pragma unroll
                    for (int o = 16; o > 0; o >>= 1)
                        mx = fmaxf(mx, __shfl_xor_sync(0xffffffffu, mx, o));
                    float e0 = __expf(v0 - mx), e1 = __expf(v1 - mx);
                    float s = e0 + e1;
                    #pragma unroll
                    for (int o = 16; o > 0; o >>= 1)
                        s += __shfl_xor_sync(0xffffffffu, s, o);
                    float inv = 1.0f / s;
                    sm[OFF_S + r * PS + l]      = tf32f(e0 * inv);
                    sm[OFF_S + r * PS + 32 + l] = tf32f(e1 * inv);
                }
            }
            barpair(barid);

            // ---- O = P V (mma tf32) -> A at col h32, tf32-rounded ----
            {
                float oacc[8];
                #pragma unroll
                for (int i = 0; i < 8; ++i) oacc[i] = 0.f;
                #pragma unroll
                for (int ks = 0; ks < 8; ++ks) {
                    const int k0 = 8 * ks;
                    unsigned a0 = lds_u(&sm[OFF_S + (pr0 + gid) * PS + k0 + tig]);
                    unsigned a1 = lds_u(&sm[OFF_S + (pr0 + 8 + gid) * PS + k0 + tig]);
                    unsigned a2 = lds_u(&sm[OFF_S + (pr0 + gid) * PS + k0 + tig + 4]);
                    unsigned a3 = lds_u(&sm[OFF_S + (pr0 + 8 + gid) * PS + k0 + tig + 4]);
                    #pragma unroll
                    for (int j = 0; j < 2; ++j) {
                        const int nn = h32 + swc * 16 + 8 * j + gid;
                        unsigned b0 = lds_u(&sm[OFF_V + (k0 + tig) * PA + nn]);
                        unsigned b1 = lds_u(&sm[OFF_V + (k0 + tig + 4) * PA + nn]);
                        mma8(oacc + j * 4, a0, a1, a2, a3, b0, b1);
                    }
                }
                #pragma unroll
                for (int j = 0; j < 2; ++j) {
                    const int col = h32 + swc * 16 + 8 * j + 2 * tig;
                    *reinterpret_cast<u64*>(&sm[OFF_A + (pr0 + gid) * PA + col]) =
                        pk2(tf32f(oacc[j*4+0]), tf32f(oacc[j*4+1]));
                    *reinterpret_cast<u64*>(&sm[OFF_A + (pr0 + 8 + gid) * PA + col]) =
                        pk2(tf32f(oacc[j*4+2]), tf32f(oacc[j*4+3]));
                }
            }
            barpair(barid);   // pair's S rows reusable next head
        }  // heads

        __syncthreads();    // all warps' O complete before merge1 reads A

        // ---- merge1: M += O_all @ W1_branch^T (mma, accumulate in M) ----
        mma_gemm<2,false>(sm, OFF_A, merge1_w + br * 192, 384, nullptr, 1.f,
                          nullptr, nullptr, M, t);
        // ends with a full barrier -> safe to overwrite A next branch
    }  // branches

    // ---- leaky relu(M) -> A (dead), tf32-rounded for merge2 ----
    #pragma unroll
    for (int j = 0; j < 12; ++j) {
        const int o = n0 + 8 * j + 2 * tig;
        float v00 = M[j*4+0], v01 = M[j*4+1], v10 = M[j*4+2], v11 = M[j*4+3];
        v00 = v00 > 0.f ? v00 : 0.2f * v00;
        v01 = v01 > 0.f ? v01 : 0.2f * v01;
        v10 = v10 > 0.f ? v10 : 0.2f * v10;
        v11 = v11 > 0.f ? v11 : 0.2f * v11;
        *reinterpret_cast<u64*>(&sm[OFF_A + r0 * PA + o]) =
            pk2(tf32f(v00), tf32f(v01));
        *reinterpret_cast<u64*>(&sm[OFF_A + (r0 + 8) * PA + o]) =
            pk2(tf32f(v10), tf32f(v11));
    }
    // merge2: T = relu(M) @ W2^T + b2 -> Q region (tf32-rounded: feeds proj)
    mma_gemm<0,true>(sm, OFF_A, merge2_w, 192, merge2_b, 1.f, sm + OFF_Q,
                     nullptr, nullptr, t);
    // proj: out = T @ Wp^T + pb -> global
    mma_gemm<1,false>(sm, OFF_Q, proj_w, 192, proj_b, 1.f, nullptr,
                      out + (size_t)w * 12288, nullptr, t);
}

extern "C" void kernel_launch(void* const* d_in, const int* in_sizes, int n_in,
                              void* d_out, int out_size) {
    const float* x        = (const float*)d_in[0];
    const float* y        = (const float*)d_in[1];
    const float* mask_x   = (const float*)d_in[2];
    const float* mask_y   = (const float*)d_in[3];
    const float* qkv_w    = (const float*)d_in[4];
    const float* qkv_b    = (const float*)d_in[5];
    const float* kv_w     = (const float*)d_in[6];
    const float* kv_b     = (const float*)d_in[7];
    const float* rpb_x    = (const float*)d_in[8];
    const float* rpb_y    = (const float*)d_in[9];
    const float* merge1_w = (const float*)d_in[10];
    const float* merge1_b = (const float*)d_in[11];
    const float* merge2_w = (const float*)d_in[12];
    const float* merge2_b = (const float*)d_in[13];
    const float* proj_w   = (const float*)d_in[14];
    const float* proj_b   = (const float*)d_in[15];
    const int*   rel_idx  = (const int*)d_in[16];
    float* out = (float*)d_out;

    cudaFuncSetAttribute(fused_attn_kernel,
                         cudaFuncAttributeMaxDynamicSharedMemorySize,
                         SMEM_FLOATS * 4);

    bias_pre_kernel<<<192, 256>>>(rpb_x, rpb_y, rel_idx);
    fused_attn_kernel<<<2048, NT, SMEM_FLOATS * 4>>>(
        x, y, mask_x, mask_y, qkv_w, qkv_b, kv_w, kv_b,
        merge1_w, merge1_b, merge2_w, merge2_b, proj_w, proj_b, out);
}

// round 16
// speedup vs baseline: 1.9542x; 1.1514x over previous
#include <cuda_runtime.h>

#define NT 256
#define PA 196            // SMEM pitch for A (196 % 32 == 4 -> conflict-free frags)
#define PS 66             // S pitch
#define PW 20             // W stage pitch (16-col chunks)

#define OFF_A   0         // 64 x PA : X/Y (tf32), per-head O (tf32), relu(M), T
#define OFF_S   12544     // 64 x PS (also W stage buffer 1 during GEMMs)
#define OFF_W0  16768     // 192 x PW = 3840
#define OFF_W1  OFF_S
#define SMEM_FLOATS 20608 // 82432 bytes -> 2 CTAs/SM

typedef unsigned long long u64;

static __device__ __forceinline__ u64 pk2(float lo, float hi) {
    u64 r; asm("mov.b64 %0,{%1,%2};" : "=l"(r) : "f"(lo), "f"(hi)); return r;
}
static __device__ __forceinline__ unsigned cvt_tf32(float f) {
    unsigned u; asm("cvt.rna.tf32.f32 %0, %1;" : "=r"(u) : "f"(f)); return u;
}
static __device__ __forceinline__ float tf32f(float f) {
    return __uint_as_float(cvt_tf32(f));
}
// D(16x8,f32) += A(16x8,row,tf32) * B(8x8 KxN, col, tf32)
static __device__ __forceinline__ void mma8(float* d, unsigned a0, unsigned a1,
                                            unsigned a2, unsigned a3,
                                            unsigned b0, unsigned b1) {
    asm("mma.sync.aligned.m16n8k8.row.col.f32.tf32.tf32.f32 "
        "{%0,%1,%2,%3}, {%4,%5,%6,%7}, {%8,%9}, {%0,%1,%2,%3};"
        : "+f"(d[0]), "+f"(d[1]), "+f"(d[2]), "+f"(d[3])
        : "r"(a0), "r"(a1), "r"(a2), "r"(a3), "r"(b0), "r"(b1));
}
static __device__ __forceinline__ void barpair(int id) {
    asm volatile("bar.sync %0, 64;" :: "r"(id) : "memory");
}
static __device__ __forceinline__ unsigned lds_u(const float* p) {
    return __float_as_uint(*p);
}

__device__ float g_bias[2 * 6 * 64 * 64];
// per-window Q/K/V scratch (written+read by the same CTA; L2-resident)
__device__ float g_Q[2048 * 64 * 192];
__device__ float g_K[2048 * 64 * 192];
__device__ float g_V[2048 * 64 * 192];

__global__ void bias_pre_kernel(const float* __restrict__ rpb_x,
                                const float* __restrict__ rpb_y,
                                const int* __restrict__ rel_idx) {
    int i = blockIdx.x * blockDim.x + threadIdx.x;
    if (i >= 2 * 6 * 4096) return;
    int br = i / (6 * 4096);
    int h  = (i / 4096) % 6;
    int nm = i & 4095;
    const float* tab = br ? rpb_y : rpb_x;
    g_bias[i] = tab[rel_idx[nm] * 6 + h];
}

// 64x192 GEMM via mma.sync tf32: dst[n][o] = (sum_c src[n][c]*W[o][c] + b)*scl.
// src in SMEM pitch PA (tf32). W row-major [o][ldw], staged per 16-col k-chunk
// (double-buffered, register prefetch, cvt.rna at stage; 1 sync per chunk).
// Warp grid 4x2: rows 16*(wid>>1).., cols 96*(wid&1)..
// DST: 0 -> global pitch 192, 2 -> accumulate into M, 4 -> SMEM pitch PA.
template<int DST, bool CVT>
static __device__ __forceinline__ void mma_gemm(
    float* sm, int srcOff, const float* __restrict__ Wg, int ldw,
    const float* __restrict__ bg, float scl,
    float* dstS, float* __restrict__ dstG, float* M, int t)
{
    const int lane = t & 31, wid = t >> 5;
    const int gid = lane >> 2, tig = lane & 3;
    const int r0 = (wid >> 1) * 16 + gid;
    const int n0 = (wid & 1) * 96;

    int wgo[3], sso[3];
    #pragma unroll
    for (int k = 0; k < 3; ++k) {
        int e = k * NT + t;
        int o = e >> 2, c4 = e & 3;
        wgo[k] = o * ldw + c4 * 4;
        sso[k] = o * PW + c4 * 4;
    }

    float dl[48];
    float* d = (DST == 2) ? M : dl;
    if (DST != 2) {
        #pragma unroll
        for (int i = 0; i < 48; ++i) dl[i] = 0.f;
    }

    float4 pre[3];
    #pragma unroll
    for (int k = 0; k < 3; ++k)
        pre[k] = *reinterpret_cast<const float4*>(&Wg[wgo[k]]);
    #pragma unroll
    for (int k = 0; k < 3; ++k) {
        float4 c;
        c.x = tf32f(pre[k].x); c.y = tf32f(pre[k].y);
        c.z = tf32f(pre[k].z); c.w = tf32f(pre[k].w);
        *reinterpret_cast<float4*>(&sm[OFF_W0 + sso[k]]) = c;
    }
    __syncthreads();

    #pragma unroll 1
    for (int ch = 0; ch < 12; ++ch) {
        if (ch < 11) {
            #pragma unroll
            for (int k = 0; k < 3; ++k)
                pre[k] = *reinterpret_cast<const float4*>(
                    &Wg[wgo[k] + (ch + 1) * 16]);
        }
        const float* wb = sm + ((ch & 1) ? OFF_W1 : OFF_W0);
        const float* sa = sm + srcOff + ch * 16;
        #pragma unroll
        for (int ks = 0; ks < 2; ++ks) {
            const int k0 = ks * 8;
            unsigned a0 = lds_u(&sa[r0 * PA + k0 + tig]);
            unsigned a1 = lds_u(&sa[(r0 + 8) * PA + k0 + tig]);
            unsigned a2 = lds_u(&sa[r0 * PA + k0 + tig + 4]);
            unsigned a3 = lds_u(&sa[(r0 + 8) * PA + k0 + tig + 4]);
            #pragma unroll
            for (int j = 0; j < 12; ++j) {
                const float* wr_ = &wb[(n0 + 8 * j + gid) * PW + k0 + tig];
                mma8(d + j * 4, a0, a1, a2, a3, lds_u(wr_), lds_u(wr_ + 4));
            }
        }
        if (ch < 11) {
            float* nb = sm + ((ch & 1) ? OFF_W0 : OFF_W1);
            #pragma unroll
            for (int k = 0; k < 3; ++k) {
                float4 c;
                c.x = tf32f(pre[k].x); c.y = tf32f(pre[k].y);
                c.z = tf32f(pre[k].z); c.w = tf32f(pre[k].w);
                *reinterpret_cast<float4*>(&nb[sso[k]]) = c;
            }
        }
        __syncthreads();
    }

    if (DST != 2) {
        #pragma unroll
        for (int j = 0; j < 12; ++j) {
            const int o = n0 + 8 * j + 2 * tig;
            float b0 = bg[o], b1 = bg[o + 1];
            float v00 = (d[j*4+0] + b0) * scl, v01 = (d[j*4+1] + b1) * scl;
            float v10 = (d[j*4+2] + b0) * scl, v11 = (d[j*4+3] + b1) * scl;
            if (CVT) {
                v00 = tf32f(v00); v01 = tf32f(v01);
                v10 = tf32f(v10); v11 = tf32f(v11);
            }
            if (DST == 0) {
                *reinterpret_cast<u64*>(&dstG[r0 * 192 + o])       = pk2(v00, v01);
                *reinterpret_cast<u64*>(&dstG[(r0 + 8) * 192 + o]) = pk2(v10, v11);
            } else {
                *reinterpret_cast<u64*>(&dstS[r0 * PA + o])        = pk2(v00, v01);
                *reinterpret_cast<u64*>(&dstS[(r0 + 8) * PA + o])  = pk2(v10, v11);
            }
        }
    }
}

__global__ void __launch_bounds__(NT, 2) fused_attn_kernel(
    const float* __restrict__ x, const float* __restrict__ y,
    const float* __restrict__ mask_x, const float* __restrict__ mask_y,
    const float* __restrict__ qkv_w, const float* __restrict__ qkv_b,
    const float* __restrict__ kv_w, const float* __restrict__ kv_b,
    const float* __restrict__ merge1_w, const float* __restrict__ merge1_b,
    const float* __restrict__ merge2_w, const float* __restrict__ merge2_b,
    const float* __restrict__ proj_w, const float* __restrict__ proj_b,
    float* __restrict__ out)
{
    extern __shared__ float sm[];
    const int t = threadIdx.x;
    const int w = blockIdx.x;
    const float scale = 0.17677669529663687f;  // 32^-0.5

    const int lane = t & 31, wid = t >> 5;
    const int gid = lane >> 2, tig = lane & 3;
    const int r0 = (wid >> 1) * 16 + gid;      // mma-gemm row mapping
    const int n0 = (wid & 1) * 96;

    // attention mappings: warp pair (wid>>1) owns rows pr0..pr0+15
    const int pr0 = (wid >> 1) * 16;
    const int swc = wid & 1;                   // col-half selector
    const int barid = 1 + (wid >> 1);

    float* qp = g_Q + (size_t)w * 12288;
    float* kp = g_K + (size_t)w * 12288;
    float* vp = g_V + (size_t)w * 12288;

    // merge1 accumulator in mma D layout
    float M[48];
    #pragma unroll
    for (int j = 0; j < 12; ++j) {
        float b0 = merge1_b[n0 + 8 * j + 2 * tig];
        float b1 = merge1_b[n0 + 8 * j + 2 * tig + 1];
        M[j*4+0] = b0; M[j*4+1] = b1; M[j*4+2] = b0; M[j*4+3] = b1;
    }

    #pragma unroll 1
    for (int br = 0; br < 2; ++br) {
        // ---- load activation (X or Y) into A, tf32-rounded ----
        {
            const float* ap = (br ? y : x) + (size_t)w * 12288;
            for (int i = t; i < 12288; i += NT) {
                int n = i / 192, c = i - n * 192;
                sm[OFF_A + n * PA + c] = tf32f(ap[i]);
            }
        }
        // mma_gemm's prologue sync orders the A stores before reads.
        if (br == 0) {
            mma_gemm<0,true>(sm, OFF_A, qkv_w,             192, qkv_b,       scale, nullptr, qp, nullptr, t);
            mma_gemm<0,true>(sm, OFF_A, qkv_w + 192 * 192, 192, qkv_b + 192, 1.f,   nullptr, kp, nullptr, t);
            mma_gemm<0,true>(sm, OFF_A, qkv_w + 384 * 192, 192, qkv_b + 384, 1.f,   nullptr, vp, nullptr, t);
        } else {
            mma_gemm<0,true>(sm, OFF_A, kv_w,              192, kv_b,        1.f,   nullptr, kp, nullptr, t);
            mma_gemm<0,true>(sm, OFF_A, kv_w + 192 * 192,  192, kv_b + 192,  1.f,   nullptr, vp, nullptr, t);
        }
        __syncthreads();   // Q/K/V global stores visible to attention reads

        const float* bias_base = g_bias + (size_t)(br * 6) * 4096;
        const float* maskp = (br ? mask_y : mask_x) + (size_t)(w & 1023) * 4096;

        #pragma unroll 1
        for (int h = 0; h < 6; ++h) {
            const int h32 = h * 32;

            // ---- S = Q K^T (mma tf32), + bias + mask in fp32 epilogue ----
            {
                float sacc[16];
                #pragma unroll
                for (int i = 0; i < 16; ++i) sacc[i] = 0.f;
                #pragma unroll
                for (int ks = 0; ks < 4; ++ks) {
                    const int k0 = 8 * ks;
                    unsigned a0 = lds_u(&qp[(pr0 + gid) * 192 + h32 + k0 + tig]);
                    unsigned a1 = lds_u(&qp[(pr0 + 8 + gid) * 192 + h32 + k0 + tig]);
                    unsigned a2 = lds_u(&qp[(pr0 + gid) * 192 + h32 + k0 + tig + 4]);
                    unsigned a3 = lds_u(&qp[(pr0 + 8 + gid) * 192 + h32 + k0 + tig + 4]);
                    #pragma unroll
                    for (int j = 0; j < 4; ++j) {
                        const int nn = swc * 32 + 8 * j + gid;
                        unsigned b0 = lds_u(&kp[nn * 192 + h32 + k0 + tig]);
                        unsigned b1 = lds_u(&kp[nn * 192 + h32 + k0 + tig + 4]);
                        mma8(sacc + j * 4, a0, a1, a2, a3, b0, b1);
                    }
                }
                const float* bb = bias_base + h * 4096;
                #pragma unroll
                for (int j = 0; j < 4; ++j) {
                    const int col = swc * 32 + 8 * j + 2 * tig;
                    float2 ba = *reinterpret_cast<const float2*>(&bb[(pr0 + gid) * 64 + col]);
                    float2 bc = *reinterpret_cast<const float2*>(&bb[(pr0 + 8 + gid) * 64 + col]);
                    float2 ma = *reinterpret_cast<const float2*>(&maskp[(pr0 + gid) * 64 + col]);
                    float2 mc = *reinterpret_cast<const float2*>(&maskp[(pr0 + 8 + gid) * 64 + col]);
                    float s0 = sacc[j*4+0] + ba.x + ma.x;
                    float s1 = sacc[j*4+1] + ba.y + ma.y;
                    float s2 = sacc[j*4+2] + bc.x + mc.x;
                    float s3 = sacc[j*4+3] + bc.y + mc.y;
                    *reinterpret_cast<u64*>(&sm[OFF_S + (pr0 + gid) * PS + col])     = pk2(s0, s1);
                    *reinterpret_cast<u64*>(&sm[OFF_S + (pr0 + 8 + gid) * PS + col]) = pk2(s2, s3);
                }
            }
            barpair(barid);

            // ---- softmax (fp32): warp handles 8 of the pair's 16 rows ----
            {
                const int l = lane;
                #pragma unroll
                for (int rr = 0; rr < 8; rr++) {
                    int r = pr0 + swc * 8 + rr;
                    float v0 = sm[OFF_S + r * PS + l];
                    float v1 = sm[OFF_S + r * PS + 32 + l];
                    float mx = fmaxf(v0, v1);
                    #pragma unroll
                    for (int o = 16; o > 0; o >>= 1)
                        mx = fmaxf(mx, __shfl_xor_sync(0xffffffffu, mx, o));
                    float e0 = __expf(v0 - mx), e1 = __expf(v1 - mx);
                    float s = e0 + e1;
                    #pragma unroll
                    for (int o = 16; o > 0; o >>= 1)
                        s += __shfl_xor_sync(0xffffffffu, s, o);
                    float inv = 1.0f / s;
                    sm[OFF_S + r * PS + l]      = tf32f(e0 * inv);
                    sm[OFF_S + r * PS + 32 + l] = tf32f(e1 * inv);
                }
            }
            barpair(barid);

            // ---- O = P V (mma tf32) -> A at col h32, tf32-rounded ----
            {
                float oacc[8];
                #pragma unroll
                for (int i = 0; i < 8; ++i) oacc[i] = 0.f;
                #pragma unroll
                for (int ks = 0; ks < 8; ++ks) {
                    const int k0 = 8 * ks;
                    unsigned a0 = lds_u(&sm[OFF_S + (pr0 + gid) * PS + k0 + tig]);
                    unsigned a1 = lds_u(&sm[OFF_S + (pr0 + 8 + gid) * PS + k0 + tig]);
                    unsigned a2 = lds_u(&sm[OFF_S + (pr0 + gid) * PS + k0 + tig + 4]);
                    unsigned a3 = lds_u(&sm[OFF_S + (pr0 + 8 + gid) * PS + k0 + tig + 4]);
                    #pragma unroll
                    for (int j = 0; j < 2; ++j) {
                        const int nn = h32 + swc * 16 + 8 * j + gid;
                        unsigned b0 = lds_u(&vp[(k0 + tig) * 192 + nn]);
                        unsigned b1 = lds_u(&vp[(k0 + tig + 4) * 192 + nn]);
                        mma8(oacc + j * 4, a0, a1, a2, a3, b0, b1);
                    }
                }
                #pragma unroll
                for (int j = 0; j < 2; ++j) {
                    const int col = h32 + swc * 16 + 8 * j + 2 * tig;
                    *reinterpret_cast<u64*>(&sm[OFF_A + (pr0 + gid) * PA + col]) =
                        pk2(tf32f(oacc[j*4+0]), tf32f(oacc[j*4+1]));
                    *reinterpret_cast<u64*>(&sm[OFF_A + (pr0 + 8 + gid) * PA + col]) =
                        pk2(tf32f(oacc[j*4+2]), tf32f(oacc[j*4+3]));
                }
            }
            barpair(barid);   // pair's S rows reusable next head
        }  // heads

        __syncthreads();    // all warps' O complete before merge1 reads A

        // ---- merge1: M += O_all @ W1_branch^T (mma, accumulate in M) ----
        mma_gemm<2,false>(sm, OFF_A, merge1_w + br * 192, 384, nullptr, 1.f,
                          nullptr, nullptr, M, t);
        // ends with a full barrier -> safe to overwrite A / g_K / g_V next branch
    }  // branches

    // ---- leaky relu(M) -> A (dead), tf32-rounded for merge2 ----
    #pragma unroll
    for (int j = 0; j < 12; ++j) {
        const int o = n0 + 8 * j + 2 * tig;
        float v00 = M[j*4+0], v01 = M[j*4+1], v10 = M[j*4+2], v11 = M[j*4+3];
        v00 = v00 > 0.f ? v00 : 0.2f * v00;
        v01 = v01 > 0.f ? v01 : 0.2f * v01;
        v10 = v10 > 0.f ? v10 : 0.2f * v10;
        v11 = v11 > 0.f ? v11 : 0.2f * v11;
        *reinterpret_cast<u64*>(&sm[OFF_A + r0 * PA + o]) =
            pk2(tf32f(v00), tf32f(v01));
        *reinterpret_cast<u64*>(&sm[OFF_A + (r0 + 8) * PA + o]) =
            pk2(tf32f(v10), tf32f(v11));
    }
    // merge2: T = relu(M) @ W2^T + b2 -> A in place (epilogue writes after all
    // reads: last chunk sync precedes epilogue). tf32-rounded: feeds proj.
    mma_gemm<4,true>(sm, OFF_A, merge2_w, 192, merge2_b, 1.f, sm + OFF_A,
                     nullptr, nullptr, t);
    // proj: out = T @ Wp^T + pb -> global (prologue sync orders T stores)
    mma_gemm<0,false>(sm, OFF_A, proj_w, 192, proj_b, 1.f, nullptr,
                      out + (size_t)w * 12288, nullptr, t);
}

extern "C" void kernel_launch(void* const* d_in, const int* in_sizes, int n_in,
                              void* d_out, int out_size) {
    const float* x        = (const float*)d_in[0];
    const float* y        = (const float*)d_in[1];
    const float* mask_x   = (const float*)d_in[2];
    const float* mask_y   = (const float*)d_in[3];
    const float* qkv_w    = (const float*)d_in[4];
    const float* qkv_b    = (const float*)d_in[5];
    const float* kv_w     = (const float*)d_in[6];
    const float* kv_b     = (const float*)d_in[7];
    const float* rpb_x    = (const float*)d_in[8];
    const float* rpb_y    = (const float*)d_in[9];
    const float* merge1_w = (const float*)d_in[10];
    const float* merge1_b = (const float*)d_in[11];
    const float* merge2_w = (const float*)d_in[12];
    const float* merge2_b = (const float*)d_in[13];
    const float* proj_w   = (const float*)d_in[14];
    const float* proj_b   = (const float*)d_in[15];
    const int*   rel_idx  = (const int*)d_in[16];
    float* out = (float*)d_out;

    cudaFuncSetAttribute(fused_attn_kernel,
                         cudaFuncAttributeMaxDynamicSharedMemorySize,
                         SMEM_FLOATS * 4);

    bias_pre_kernel<<<192, 256>>>(rpb_x, rpb_y, rel_idx);
    fused_attn_kernel<<<2048, NT, SMEM_FLOATS * 4>>>(
        x, y, mask_x, mask_y, qkv_w, qkv_b, kv_w, kv_b,
        merge1_w, merge1_b, merge2_w, merge2_b, proj_w, proj_b, out);
}

// round 17
// speedup vs baseline: 2.0623x; 1.0553x over previous
#include <cuda_runtime.h>

#define NT 256
#define PA 196            // SMEM pitch for A (196 % 32 == 4 -> conflict-free frags)
#define PS 66             // S pitch
#define PW 20             // W stage pitch (16-col chunks)
#define PH 36             // per-head Q/K/V stage pitch (conflict-free frags)

#define OFF_A   0         // 64 x PA : X/Y (tf32), per-head O (tf32), relu(M), T
#define OFF_S   12544     // 64 x PS (also W stage buffer 1 during GEMMs)
#define OFF_W0  16768     // 192 x PW = 3840
#define OFF_W1  OFF_S
#define OFF_QS  20608     // 64 x PH : Q_h stage
#define OFF_KS  22912     // 64 x PH : K_h stage
#define OFF_VS  25216     // 64 x PH : V_h stage
#define SMEM_FLOATS 27520 // 110080 bytes -> still 2 CTAs/SM

typedef unsigned long long u64;

static __device__ __forceinline__ u64 pk2(float lo, float hi) {
    u64 r; asm("mov.b64 %0,{%1,%2};" : "=l"(r) : "f"(lo), "f"(hi)); return r;
}
static __device__ __forceinline__ unsigned cvt_tf32(float f) {
    unsigned u; asm("cvt.rna.tf32.f32 %0, %1;" : "=r"(u) : "f"(f)); return u;
}
static __device__ __forceinline__ float tf32f(float f) {
    return __uint_as_float(cvt_tf32(f));
}
// D(16x8,f32) += A(16x8,row,tf32) * B(8x8 KxN, col, tf32)
static __device__ __forceinline__ void mma8(float* d, unsigned a0, unsigned a1,
                                            unsigned a2, unsigned a3,
                                            unsigned b0, unsigned b1) {
    asm("mma.sync.aligned.m16n8k8.row.col.f32.tf32.tf32.f32 "
        "{%0,%1,%2,%3}, {%4,%5,%6,%7}, {%8,%9}, {%0,%1,%2,%3};"
        : "+f"(d[0]), "+f"(d[1]), "+f"(d[2]), "+f"(d[3])
        : "r"(a0), "r"(a1), "r"(a2), "r"(a3), "r"(b0), "r"(b1));
}
static __device__ __forceinline__ void barpair(int id) {
    asm volatile("bar.sync %0, 64;" :: "r"(id) : "memory");
}
static __device__ __forceinline__ unsigned lds_u(const float* p) {
    return __float_as_uint(*p);
}

__device__ float g_bias[2 * 6 * 64 * 64];
// per-window Q/K/V scratch (written+read by the same CTA; L2-resident)
__device__ float g_Q[2048 * 64 * 192];
__device__ float g_K[2048 * 64 * 192];
__device__ float g_V[2048 * 64 * 192];

__global__ void bias_pre_kernel(const float* __restrict__ rpb_x,
                                const float* __restrict__ rpb_y,
                                const int* __restrict__ rel_idx) {
    int i = blockIdx.x * blockDim.x + threadIdx.x;
    if (i >= 2 * 6 * 4096) return;
    int br = i / (6 * 4096);
    int h  = (i / 4096) % 6;
    int nm = i & 4095;
    const float* tab = br ? rpb_y : rpb_x;
    g_bias[i] = tab[rel_idx[nm] * 6 + h];
}

// 64x192 GEMM via mma.sync tf32 (see R14-16).
// DST: 0 -> global pitch 192, 2 -> accumulate into M, 4 -> SMEM pitch PA.
template<int DST, bool CVT>
static __device__ __forceinline__ void mma_gemm(
    float* sm, int srcOff, const float* __restrict__ Wg, int ldw,
    const float* __restrict__ bg, float scl,
    float* dstS, float* __restrict__ dstG, float* M, int t)
{
    const int lane = t & 31, wid = t >> 5;
    const int gid = lane >> 2, tig = lane & 3;
    const int r0 = (wid >> 1) * 16 + gid;
    const int n0 = (wid & 1) * 96;

    int wgo[3], sso[3];
    #pragma unroll
    for (int k = 0; k < 3; ++k) {
        int e = k * NT + t;
        int o = e >> 2, c4 = e & 3;
        wgo[k] = o * ldw + c4 * 4;
        sso[k] = o * PW + c4 * 4;
    }

    float dl[48];
    float* d = (DST == 2) ? M : dl;
    if (DST != 2) {
        #pragma unroll
        for (int i = 0; i < 48; ++i) dl[i] = 0.f;
    }

    float4 pre[3];
    #pragma unroll
    for (int k = 0; k < 3; ++k)
        pre[k] = *reinterpret_cast<const float4*>(&Wg[wgo[k]]);
    #pragma unroll
    for (int k = 0; k < 3; ++k) {
        float4 c;
        c.x = tf32f(pre[k].x); c.y = tf32f(pre[k].y);
        c.z = tf32f(pre[k].z); c.w = tf32f(pre[k].w);
        *reinterpret_cast<float4*>(&sm[OFF_W0 + sso[k]]) = c;
    }
    __syncthreads();

    #pragma unroll 1
    for (int ch = 0; ch < 12; ++ch) {
        if (ch < 11) {
            #pragma unroll
            for (int k = 0; k < 3; ++k)
                pre[k] = *reinterpret_cast<const float4*>(
                    &Wg[wgo[k] + (ch + 1) * 16]);
        }
        const float* wb = sm + ((ch & 1) ? OFF_W1 : OFF_W0);
        const float* sa = sm + srcOff + ch * 16;
        #pragma unroll
        for (int ks = 0; ks < 2; ++ks) {
            const int k0 = ks * 8;
            unsigned a0 = lds_u(&sa[r0 * PA + k0 + tig]);
            unsigned a1 = lds_u(&sa[(r0 + 8) * PA + k0 + tig]);
            unsigned a2 = lds_u(&sa[r0 * PA + k0 + tig + 4]);
            unsigned a3 = lds_u(&sa[(r0 + 8) * PA + k0 + tig + 4]);
            #pragma unroll
            for (int j = 0; j < 12; ++j) {
                const float* wr_ = &wb[(n0 + 8 * j + gid) * PW + k0 + tig];
                mma8(d + j * 4, a0, a1, a2, a3, lds_u(wr_), lds_u(wr_ + 4));
            }
        }
        if (ch < 11) {
            float* nb = sm + ((ch & 1) ? OFF_W0 : OFF_W1);
            #pragma unroll
            for (int k = 0; k < 3; ++k) {
                float4 c;
                c.x = tf32f(pre[k].x); c.y = tf32f(pre[k].y);
                c.z = tf32f(pre[k].z); c.w = tf32f(pre[k].w);
                *reinterpret_cast<float4*>(&nb[sso[k]]) = c;
            }
        }
        __syncthreads();
    }

    if (DST != 2) {
        #pragma unroll
        for (int j = 0; j < 12; ++j) {
            const int o = n0 + 8 * j + 2 * tig;
            float b0 = bg[o], b1 = bg[o + 1];
            float v00 = (d[j*4+0] + b0) * scl, v01 = (d[j*4+1] + b1) * scl;
            float v10 = (d[j*4+2] + b0) * scl, v11 = (d[j*4+3] + b1) * scl;
            if (CVT) {
                v00 = tf32f(v00); v01 = tf32f(v01);
                v10 = tf32f(v10); v11 = tf32f(v11);
            }
            if (DST == 0) {
                *reinterpret_cast<u64*>(&dstG[r0 * 192 + o])       = pk2(v00, v01);
                *reinterpret_cast<u64*>(&dstG[(r0 + 8) * 192 + o]) = pk2(v10, v11);
            } else {
                *reinterpret_cast<u64*>(&dstS[r0 * PA + o])        = pk2(v00, v01);
                *reinterpret_cast<u64*>(&dstS[(r0 + 8) * PA + o])  = pk2(v10, v11);
            }
        }
    }
}

__global__ void __launch_bounds__(NT, 2) fused_attn_kernel(
    const float* __restrict__ x, const float* __restrict__ y,
    const float* __restrict__ mask_x, const float* __restrict__ mask_y,
    const float* __restrict__ qkv_w, const float* __restrict__ qkv_b,
    const float* __restrict__ kv_w, const float* __restrict__ kv_b,
    const float* __restrict__ merge1_w, const float* __restrict__ merge1_b,
    const float* __restrict__ merge2_w, const float* __restrict__ merge2_b,
    const float* __restrict__ proj_w, const float* __restrict__ proj_b,
    float* __restrict__ out)
{
    extern __shared__ float sm[];
    const int t = threadIdx.x;
    const int w = blockIdx.x;
    const float scale = 0.17677669529663687f;  // 32^-0.5

    const int lane = t & 31, wid = t >> 5;
    const int gid = lane >> 2, tig = lane & 3;
    const int r0 = (wid >> 1) * 16 + gid;      // mma-gemm row mapping
    const int n0 = (wid & 1) * 96;

    // attention mappings: warp pair (wid>>1) owns rows pr0..pr0+15
    const int pr0 = (wid >> 1) * 16;
    const int swc = wid & 1;                   // col-half selector
    const int barid = 1 + (wid >> 1);

    float* qp = g_Q + (size_t)w * 12288;
    float* kp = g_K + (size_t)w * 12288;
    float* vp = g_V + (size_t)w * 12288;

    // merge1 accumulator in mma D layout
    float M[48];
    #pragma unroll
    for (int j = 0; j < 12; ++j) {
        float b0 = merge1_b[n0 + 8 * j + 2 * tig];
        float b1 = merge1_b[n0 + 8 * j + 2 * tig + 1];
        M[j*4+0] = b0; M[j*4+1] = b1; M[j*4+2] = b0; M[j*4+3] = b1;
    }

    #pragma unroll 1
    for (int br = 0; br < 2; ++br) {
        // ---- load activation (X or Y) into A, tf32-rounded ----
        {
            const float* ap = (br ? y : x) + (size_t)w * 12288;
            for (int i = t; i < 12288; i += NT) {
                int n = i / 192, c = i - n * 192;
                sm[OFF_A + n * PA + c] = tf32f(ap[i]);
            }
        }
        // mma_gemm's prologue sync orders the A stores before reads.
        if (br == 0) {
            mma_gemm<0,true>(sm, OFF_A, qkv_w,             192, qkv_b,       scale, nullptr, qp, nullptr, t);
            mma_gemm<0,true>(sm, OFF_A, qkv_w + 192 * 192, 192, qkv_b + 192, 1.f,   nullptr, kp, nullptr, t);
            mma_gemm<0,true>(sm, OFF_A, qkv_w + 384 * 192, 192, qkv_b + 384, 1.f,   nullptr, vp, nullptr, t);
        } else {
            mma_gemm<0,true>(sm, OFF_A, kv_w,              192, kv_b,        1.f,   nullptr, kp, nullptr, t);
            mma_gemm<0,true>(sm, OFF_A, kv_w + 192 * 192,  192, kv_b + 192,  1.f,   nullptr, vp, nullptr, t);
        }
        __syncthreads();   // Q/K/V global stores visible to staging reads

        const float* bias_base = g_bias + (size_t)(br * 6) * 4096;
        const float* maskp = (br ? mask_y : mask_x) + (size_t)(w & 1023) * 4096;

        #pragma unroll 1
        for (int h = 0; h < 6; ++h) {
            const int h32 = h * 32;

            // ---- stage Q_h, K_h, V_h (64x32 each) into SMEM, pitch PH ----
            // coalesced float4 loads; conflict-free STS (quarter-warp phases)
            {
                #pragma unroll
                for (int k = 0; k < 2; ++k) {
                    int e = k * NT + t;           // 0..511 float4 per tensor
                    int row = e >> 3, c4 = (e & 7) * 4;
                    float4 qv = *reinterpret_cast<const float4*>(&qp[row * 192 + h32 + c4]);
                    float4 kv = *reinterpret_cast<const float4*>(&kp[row * 192 + h32 + c4]);
                    float4 vv = *reinterpret_cast<const float4*>(&vp[row * 192 + h32 + c4]);
                    *reinterpret_cast<float4*>(&sm[OFF_QS + row * PH + c4]) = qv;
                    *reinterpret_cast<float4*>(&sm[OFF_KS + row * PH + c4]) = kv;
                    *reinterpret_cast<float4*>(&sm[OFF_VS + row * PH + c4]) = vv;
                }
            }
            __syncthreads();   // stage visible to all warps

            // ---- S = Q_h K_h^T (mma tf32, frags via conflict-free LDS) ----
            {
                float sacc[16];
                #pragma unroll
                for (int i = 0; i < 16; ++i) sacc[i] = 0.f;
                #pragma unroll
                for (int ks = 0; ks < 4; ++ks) {
                    const int k0 = 8 * ks;
                    unsigned a0 = lds_u(&sm[OFF_QS + (pr0 + gid) * PH + k0 + tig]);
                    unsigned a1 = lds_u(&sm[OFF_QS + (pr0 + 8 + gid) * PH + k0 + tig]);
                    unsigned a2 = lds_u(&sm[OFF_QS + (pr0 + gid) * PH + k0 + tig + 4]);
                    unsigned a3 = lds_u(&sm[OFF_QS + (pr0 + 8 + gid) * PH + k0 + tig + 4]);
                    #pragma unroll
                    for (int j = 0; j < 4; ++j) {
                        const int nn = swc * 32 + 8 * j + gid;
                        unsigned b0 = lds_u(&sm[OFF_KS + nn * PH + k0 + tig]);
                        unsigned b1 = lds_u(&sm[OFF_KS + nn * PH + k0 + tig + 4]);
                        mma8(sacc + j * 4, a0, a1, a2, a3, b0, b1);
                    }
                }
                const float* bb = bias_base + h * 4096;
                #pragma unroll
                for (int j = 0; j < 4; ++j) {
                    const int col = swc * 32 + 8 * j + 2 * tig;
                    float2 ba = *reinterpret_cast<const float2*>(&bb[(pr0 + gid) * 64 + col]);
                    float2 bc = *reinterpret_cast<const float2*>(&bb[(pr0 + 8 + gid) * 64 + col]);
                    float2 ma = *reinterpret_cast<const float2*>(&maskp[(pr0 + gid) * 64 + col]);
                    float2 mc = *reinterpret_cast<const float2*>(&maskp[(pr0 + 8 + gid) * 64 + col]);
                    float s0 = sacc[j*4+0] + ba.x + ma.x;
                    float s1 = sacc[j*4+1] + ba.y + ma.y;
                    float s2 = sacc[j*4+2] + bc.x + mc.x;
                    float s3 = sacc[j*4+3] + bc.y + mc.y;
                    *reinterpret_cast<u64*>(&sm[OFF_S + (pr0 + gid) * PS + col])     = pk2(s0, s1);
                    *reinterpret_cast<u64*>(&sm[OFF_S + (pr0 + 8 + gid) * PS + col]) = pk2(s2, s3);
                }
            }
            barpair(barid);

            // ---- softmax (fp32): warp handles 8 of the pair's 16 rows ----
            {
                const int l = lane;
                #pragma unroll
                for (int rr = 0; rr < 8; rr++) {
                    int r = pr0 + swc * 8 + rr;
                    float v0 = sm[OFF_S + r * PS + l];
                    float v1 = sm[OFF_S + r * PS + 32 + l];
                    float mx = fmaxf(v0, v1);
                    #pragma unroll
                    for (int o = 16; o > 0; o >>= 1)
                        mx = fmaxf(mx, __shfl_xor_sync(0xffffffffu, mx, o));
                    float e0 = __expf(v0 - mx), e1 = __expf(v1 - mx);
                    float s = e0 + e1;
                    #pragma unroll
                    for (int o = 16; o > 0; o >>= 1)
                        s += __shfl_xor_sync(0xffffffffu, s, o);
                    float inv = 1.0f / s;
                    sm[OFF_S + r * PS + l]      = tf32f(e0 * inv);
                    sm[OFF_S + r * PS + 32 + l] = tf32f(e1 * inv);
                }
            }
            barpair(barid);

            // ---- O = P V_h (mma tf32, V frags via LDS) -> A at col h32 ----
            {
                float oacc[8];
                #pragma unroll
                for (int i = 0; i < 8; ++i) oacc[i] = 0.f;
                #pragma unroll
                for (int ks = 0; ks < 8; ++ks) {
                    const int k0 = 8 * ks;
                    unsigned a0 = lds_u(&sm[OFF_S + (pr0 + gid) * PS + k0 + tig]);
                    unsigned a1 = lds_u(&sm[OFF_S + (pr0 + 8 + gid) * PS + k0 + tig]);
                    unsigned a2 = lds_u(&sm[OFF_S + (pr0 + gid) * PS + k0 + tig + 4]);
                    unsigned a3 = lds_u(&sm[OFF_S + (pr0 + 8 + gid) * PS + k0 + tig + 4]);
                    #pragma unroll
                    for (int j = 0; j < 2; ++j) {
                        const int nn = swc * 16 + 8 * j + gid;
                        unsigned b0 = lds_u(&sm[OFF_VS + (k0 + tig) * PH + nn]);
                        unsigned b1 = lds_u(&sm[OFF_VS + (k0 + tig + 4) * PH + nn]);
                        mma8(oacc + j * 4, a0, a1, a2, a3, b0, b1);
                    }
                }
                #pragma unroll
                for (int j = 0; j < 2; ++j) {
                    const int col = h32 + swc * 16 + 8 * j + 2 * tig;
                    *reinterpret_cast<u64*>(&sm[OFF_A + (pr0 + gid) * PA + col]) =
                        pk2(tf32f(oacc[j*4+0]), tf32f(oacc[j*4+1]));
                    *reinterpret_cast<u64*>(&sm[OFF_A + (pr0 + 8 + gid) * PA + col]) =
                        pk2(tf32f(oacc[j*4+2]), tf32f(oacc[j*4+3]));
                }
            }
            __syncthreads();   // all PV reads done before next head's restage
        }  // heads

        // ---- merge1: M += O_all @ W1_branch^T (mma, accumulate in M) ----
        // (trailing head sync orders O writes before merge1 reads A)
        mma_gemm<2,false>(sm, OFF_A, merge1_w + br * 192, 384, nullptr, 1.f,
                          nullptr, nullptr, M, t);
        // ends with a full barrier -> safe to overwrite A / g_K / g_V next branch
    }  // branches

    // ---- leaky relu(M) -> A (dead), tf32-rounded for merge2 ----
    #pragma unroll
    for (int j = 0; j < 12; ++j) {
        const int o = n0 + 8 * j + 2 * tig;
        float v00 = M[j*4+0], v01 = M[j*4+1], v10 = M[j*4+2], v11 = M[j*4+3];
        v00 = v00 > 0.f ? v00 : 0.2f * v00;
        v01 = v01 > 0.f ? v01 : 0.2f * v01;
        v10 = v10 > 0.f ? v10 : 0.2f * v10;
        v11 = v11 > 0.f ? v11 : 0.2f * v11;
        *reinterpret_cast<u64*>(&sm[OFF_A + r0 * PA + o]) =
            pk2(tf32f(v00), tf32f(v01));
        *reinterpret_cast<u64*>(&sm[OFF_A + (r0 + 8) * PA + o]) =
            pk2(tf32f(v10), tf32f(v11));
    }
    // merge2: T = relu(M) @ W2^T + b2 -> A in place (epilogue after last sync)
    mma_gemm<4,true>(sm, OFF_A, merge2_w, 192, merge2_b, 1.f, sm + OFF_A,
                     nullptr, nullptr, t);
    // proj: out = T @ Wp^T + pb -> global (prologue sync orders T stores)
    mma_gemm<0,false>(sm, OFF_A, proj_w, 192, proj_b, 1.f, nullptr,
                      out + (size_t)w * 12288, nullptr, t);
}

extern "C" void kernel_launch(void* const* d_in, const int* in_sizes, int n_in,
                              void* d_out, int out_size) {
    const float* x        = (const float*)d_in[0];
    const float* y        = (const float*)d_in[1];
    const float* mask_x   = (const float*)d_in[2];
    const float* mask_y   = (const float*)d_in[3];
    const float* qkv_w    = (const float*)d_in[4];
    const float* qkv_b    = (const float*)d_in[5];
    const float* kv_w     = (const float*)d_in[6];
    const float* kv_b     = (const float*)d_in[7];
    const float* rpb_x    = (const float*)d_in[8];
    const float* rpb_y    = (const float*)d_in[9];
    const float* merge1_w = (const float*)d_in[10];
    const float* merge1_b = (const float*)d_in[11];
    const float* merge2_w = (const float*)d_in[12];
    const float* merge2_b = (const float*)d_in[13];
    const float* proj_w   = (const float*)d_in[14];
    const float* proj_b   = (const float*)d_in[15];
    const int*   rel_idx  = (const int*)d_in[16];
    float* out = (float*)d_out;

    cudaFuncSetAttribute(fused_attn_kernel,
                         cudaFuncAttributeMaxDynamicSharedMemorySize,
                         SMEM_FLOATS * 4);

    bias_pre_kernel<<<192, 256>>>(rpb_x, rpb_y, rel_idx);
    fused_attn_kernel<<<2048, NT, SMEM_FLOATS * 4>>>(
        x, y, mask_x, mask_y, qkv_w, qkv_b, kv_w, kv_b,
        merge1_w, merge1_b, merge2_w, merge2_b, proj_w, proj_b, out);
}